// round 13
// baseline (speedup 1.0000x reference)
#include <cuda_runtime.h>
#include <cuda_bf16.h>
#include <math.h>
#include <cstdint>

// ---------------- problem dims (fixed) ----------------
#define BB   2
#define SS   2048
#define DD   768
#define HH   12
#define DK   64
#define FF   3072
#define MM   (BB*SS)          // 4096 tokens
#define NQKV (3*DD)           // 2304 fused QKV cols

// ---------------- scratch (device globals; allocation-free) ----------------
__device__ float g_h[MM*DD];            // LN1 output (tf32-rounded)
__device__ float g_qkv[MM*NQKV];        // fused QKV [M, 2304] (tf32-rounded)
__device__ __nv_bfloat16 g_vt16[BB*HH*DK*SS]; // V transposed [bh][d][s], bf16
__device__ float g_o[MM*DD];            // attn output (tf32-rounded)
__device__ float g_y[MM*DD];            // after O-proj + residual (fp32)
__device__ float g_z[MM*DD];            // LN2 output (tf32-rounded)
__device__ float g_u[MM*FF];            // FFN hidden (tf32-rounded)
__device__ float g_wtq[NQKV*DD];        // fused QKV weights^T (tf32)
__device__ float g_btq[NQKV];           // fused QKV bias
__device__ float g_wto[DD*DD];          // wo^T (tf32)
__device__ float g_wt1[FF*DD];          // w1^T (tf32)
__device__ float g_wt2[DD*FF];          // w2^T (tf32)

// ================= helpers =================
__device__ __forceinline__ uint32_t f2tf(float f) {
    uint32_t u; asm("cvt.rna.tf32.f32 %0, %1;" : "=r"(u) : "f"(f)); return u;
}
__device__ __forceinline__ float f2tff(float f) { return __uint_as_float(f2tf(f)); }
__device__ __forceinline__ void mma8(float* c, const uint32_t* a, const uint32_t* b) {
    asm volatile("mma.sync.aligned.m16n8k8.row.col.f32.tf32.tf32.f32 "
        "{%0,%1,%2,%3}, {%4,%5,%6,%7}, {%8,%9}, {%0,%1,%2,%3};"
        : "+f"(c[0]), "+f"(c[1]), "+f"(c[2]), "+f"(c[3])
        : "r"(a[0]), "r"(a[1]), "r"(a[2]), "r"(a[3]), "r"(b[0]), "r"(b[1]));
}
__device__ __forceinline__ void mma16bf(float* c, const uint32_t* a, const uint32_t* b) {
    asm volatile("mma.sync.aligned.m16n8k16.row.col.f32.bf16.bf16.f32 "
        "{%0,%1,%2,%3}, {%4,%5,%6,%7}, {%8,%9}, {%0,%1,%2,%3};"
        : "+f"(c[0]), "+f"(c[1]), "+f"(c[2]), "+f"(c[3])
        : "r"(a[0]), "r"(a[1]), "r"(a[2]), "r"(a[3]), "r"(b[0]), "r"(b[1]));
}
// pack: lo -> bits[15:0], hi -> bits[31:16]
__device__ __forceinline__ uint32_t packbf(float lo, float hi) {
    uint32_t d;
    asm("cvt.rn.bf16x2.f32 %0, %1, %2;" : "=r"(d) : "f"(hi), "f"(lo));
    return d;
}
__device__ __forceinline__ float gelu_f(float v) {
    return 0.5f * v * (1.0f + erff(v * 0.70710678118654752f));
}

// ---------------- LayerNorm: one block per row, tf32-rounded output -------
__global__ void __launch_bounds__(256) ln_kernel(
    const float* __restrict__ x, const float* __restrict__ gw,
    const float* __restrict__ bw, float* __restrict__ out)
{
    __shared__ float red[8];
    int row = blockIdx.x;
    int tid = threadIdx.x;
    const float* xr = x + (size_t)row * DD;

    float v0 = xr[tid], v1 = xr[tid + 256], v2 = xr[tid + 512];
    float s = v0 + v1 + v2;
    #pragma unroll
    for (int o = 16; o > 0; o >>= 1) s += __shfl_xor_sync(0xffffffffu, s, o);
    if ((tid & 31) == 0) red[tid >> 5] = s;
    __syncthreads();
    float tot = red[0]+red[1]+red[2]+red[3]+red[4]+red[5]+red[6]+red[7];
    float mu = tot * (1.0f / 768.0f);
    float d0 = v0 - mu, d1 = v1 - mu, d2 = v2 - mu;
    float q = d0*d0 + d1*d1 + d2*d2;
    #pragma unroll
    for (int o = 16; o > 0; o >>= 1) q += __shfl_xor_sync(0xffffffffu, q, o);
    __syncthreads();
    if ((tid & 31) == 0) red[tid >> 5] = q;
    __syncthreads();
    float vtot = red[0]+red[1]+red[2]+red[3]+red[4]+red[5]+red[6]+red[7];
    float rstd = rsqrtf(vtot * (1.0f / 768.0f) + 1e-5f);
    float* orow = out + (size_t)row * DD;
    orow[tid]       = f2tff(d0 * rstd * gw[tid]       + bw[tid]);
    orow[tid + 256] = f2tff(d1 * rstd * gw[tid + 256] + bw[tid + 256]);
    orow[tid + 512] = f2tff(d2 * rstd * gw[tid + 512] + bw[tid + 512]);
}

// ---------------- weight prep: transposes + packs (tf32) ------------------
__device__ __forceinline__ void trans_tile(
    const float* __restrict__ W, float* __restrict__ Wt, int K, int N,
    int bx, int by, float t[32][33], int tx, int ty)
{
    #pragma unroll
    for (int l = 0; l < 4; l++) {
        int k = by * 32 + ty + l * 8;
        t[ty + l * 8][tx] = W[(size_t)k * N + bx * 32 + tx];
    }
    __syncthreads();
    #pragma unroll
    for (int l = 0; l < 4; l++) {
        int n = bx * 32 + ty + l * 8;
        Wt[(size_t)n * K + by * 32 + tx] = f2tff(t[tx][ty + l * 8]);
    }
}

// grid: 1728 (qkv) + 576 (wo) + 2304 (w1) + 2304 (w2) = 6912
__global__ void __launch_bounds__(256) prep_w_kernel(
    const float* __restrict__ wq, const float* __restrict__ wk,
    const float* __restrict__ wv, const float* __restrict__ wo,
    const float* __restrict__ w1, const float* __restrict__ w2,
    float* __restrict__ wtq, float* __restrict__ wto,
    float* __restrict__ wt1, float* __restrict__ wt2)
{
    __shared__ float t[32][33];
    int id = blockIdx.x;
    int tx = threadIdx.x, ty = threadIdx.y;
    if (id < 1728) {
        int p = id / 576, rem = id % 576;
        int bx = rem % 24, by = rem / 24;
        const float* wp = (p == 0) ? wq : (p == 1) ? wk : wv;
        int np0 = bx * 32, d0 = by * 32;
        int hh = np0 >> 6, kk0 = np0 & 63;
        #pragma unroll
        for (int l = 0; l < 4; l++) {
            int d = d0 + ty + l * 8;
            t[ty + l * 8][tx] = wp[((size_t)hh * DD + d) * DK + kk0 + tx];
        }
        __syncthreads();
        #pragma unroll
        for (int l = 0; l < 4; l++) {
            int n = np0 + ty + l * 8;
            wtq[((size_t)p * DD + n) * DD + d0 + tx] = f2tff(t[tx][ty + l * 8]);
        }
    } else if (id < 2304) {
        int rem = id - 1728;
        trans_tile(wo, wto, DD, DD, rem % 24, rem / 24, t, tx, ty);
    } else if (id < 4608) {
        int rem = id - 2304;
        trans_tile(w1, wt1, DD, FF, rem % 96, rem / 96, t, tx, ty);
    } else {
        int rem = id - 4608;
        trans_tile(w2, wt2, FF, DD, rem % 24, rem / 24, t, tx, ty);
    }
}

__global__ void qkv_bias_kernel(
    const float* __restrict__ bq, const float* __restrict__ bk,
    const float* __restrict__ bv, float* __restrict__ bt)
{
    int i = blockIdx.x * 256 + threadIdx.x;   // <<<3, 256>>>... grid 3*DD/256
    if (i < DD) { bt[i] = bq[i]; bt[DD + i] = bk[i]; bt[2 * DD + i] = bv[i]; }
}

// ---------------- V transpose: qkv V-part -> vt16[bh][d][s] bf16 ----------
__global__ void __launch_bounds__(256) vtrans_kernel(
    const float* __restrict__ qkv, __nv_bfloat16* __restrict__ vt16)
{
    __shared__ float t[32][33];
    int s0 = blockIdx.x * 32;
    int d0 = blockIdx.y * 32;
    int bh = blockIdx.z;
    int b_ = bh / HH, h_ = bh % HH;
    int tx = threadIdx.x, ty = threadIdx.y;
    #pragma unroll
    for (int l = 0; l < 4; l++) {
        int s = s0 + ty + l * 8;
        t[ty + l * 8][tx] = qkv[((size_t)(b_ * SS + s)) * NQKV + 2 * DD + h_ * 64 + d0 + tx];
    }
    __syncthreads();
    if (tx < 16) {
        #pragma unroll
        for (int l = 0; l < 4; l++) {
            int d = d0 + ty + l * 8;
            uint32_t w = packbf(t[2 * tx][ty + l * 8], t[2 * tx + 1][ty + l * 8]);
            uint32_t* orow = (uint32_t*)(vt16 + ((size_t)bh * 64 + d) * SS + s0);
            orow[tx] = w;
        }
    }
}

// ============ TF32 mma.sync GEMM (unchanged — known good) =================
#define GEMM_SMEM (16384 * 4)

template<bool GELU, bool RES, bool TFOUT>
__global__ void __launch_bounds__(256, 2) tc_gemm(
    const float* __restrict__ A, const float* __restrict__ Bt,
    const float* __restrict__ bias, const float* __restrict__ res,
    float* __restrict__ C, int N, int K)
{
    extern __shared__ uint32_t sh[];
    uint32_t* sA = sh;          // [2][4096]
    uint32_t* sB = sh + 8192;   // [2][4096]
    int tid = threadIdx.x, lane = tid & 31, wid = tid >> 5;
    int wm = wid & 1, wn = wid >> 1;
    int bm = blockIdx.y, bn = blockIdx.x;

    const float* Ag = A  + (size_t)(bm * 128) * K;
    const float* Bg = Bt + (size_t)(bn * 128) * K;

    int ksw = (tid & 7) >> 1;
    int oa0 = ((0 ^ ksw) << 2), oa1 = ((1 ^ ksw) << 2),
        oa2 = ((2 ^ ksw) << 2), oa3 = ((3 ^ ksw) << 2);
    int ob0 = ((0 ^ ksw) << 1), ob1 = ((1 ^ ksw) << 1),
        ob2 = ((2 ^ ksw) << 1), ob3 = ((3 ^ ksw) << 1);
    int aD[4], aS[4], bD[4];
    #pragma unroll
    for (int i = 0; i < 4; i++) {
        int idx = tid + i * 256;
        int r = idx >> 3, cg = idx & 7;
        int ks = cg >> 1, hf = cg & 1;
        int ma = r >> 4, row = r & 15;
        aD[i] = ((ma * 4 + ks) * 32 + (row & 7) * 4) * 4 + (row >> 3) + 2 * hf;
        aS[i] = r * K + cg * 4;
        int na = r >> 3, nn = r & 7;
        bD[i] = ((na * 4 + ks) * 32 + nn * 4) * 2 + hf;
    }

    float acc[4][4][4];
    #pragma unroll
    for (int mi = 0; mi < 4; mi++)
        #pragma unroll
        for (int ni = 0; ni < 4; ni++)
            #pragma unroll
            for (int r = 0; r < 4; r++) acc[mi][ni][r] = 0.0f;

    #pragma unroll
    for (int i = 0; i < 4; i++) {
        float4 v = *(const float4*)(Ag + aS[i]);
        sA[aD[i]+oa0] = __float_as_uint(v.x); sA[aD[i]+oa1] = __float_as_uint(v.y);
        sA[aD[i]+oa2] = __float_as_uint(v.z); sA[aD[i]+oa3] = __float_as_uint(v.w);
        float4 w = *(const float4*)(Bg + aS[i]);
        sB[bD[i]+ob0] = __float_as_uint(w.x); sB[bD[i]+ob1] = __float_as_uint(w.y);
        sB[bD[i]+ob2] = __float_as_uint(w.z); sB[bD[i]+ob3] = __float_as_uint(w.w);
    }
    __syncthreads();

    int NT = K >> 5;
    for (int t = 0; t < NT; t++) {
        float4 pa[4], pb[4];
        bool pf = (t + 1 < NT);
        if (pf) {
            int k0 = (t + 1) * 32;
            #pragma unroll
            for (int i = 0; i < 4; i++) {
                pa[i] = *(const float4*)(Ag + aS[i] + k0);
                pb[i] = *(const float4*)(Bg + aS[i] + k0);
            }
        }
        const uint32_t* cA = sA + (t & 1) * 4096;
        const uint32_t* cB = sB + (t & 1) * 4096;
        #pragma unroll
        for (int ks = 0; ks < 4; ks++) {
            int lx = lane ^ ks;
            uint32_t ua[4][4], ub[4][2];
            #pragma unroll
            for (int mi = 0; mi < 4; mi++)
                *(uint4*)ua[mi] = *(const uint4*)&cA[(((wm*4+mi)*4 + ks)*32 + lx)*4];
            #pragma unroll
            for (int ni = 0; ni < 4; ni++)
                *(uint2*)ub[ni] = *(const uint2*)&cB[(((wn*4+ni)*4 + ks)*32 + lx)*2];
            #pragma unroll
            for (int mi = 0; mi < 4; mi++)
                #pragma unroll
                for (int ni = 0; ni < 4; ni++)
                    mma8(acc[mi][ni], ua[mi], ub[ni]);
        }
        if (pf) {
            uint32_t* nA = sA + ((t + 1) & 1) * 4096;
            uint32_t* nB = sB + ((t + 1) & 1) * 4096;
            #pragma unroll
            for (int i = 0; i < 4; i++) {
                nA[aD[i]+oa0] = __float_as_uint(pa[i].x); nA[aD[i]+oa1] = __float_as_uint(pa[i].y);
                nA[aD[i]+oa2] = __float_as_uint(pa[i].z); nA[aD[i]+oa3] = __float_as_uint(pa[i].w);
                nB[bD[i]+ob0] = __float_as_uint(pb[i].x); nB[bD[i]+ob1] = __float_as_uint(pb[i].y);
                nB[bD[i]+ob2] = __float_as_uint(pb[i].z); nB[bD[i]+ob3] = __float_as_uint(pb[i].w);
            }
        }
        __syncthreads();
    }

    int g = lane >> 2, T = lane & 3;
    #pragma unroll
    for (int mi = 0; mi < 4; mi++) {
        int row0 = bm * 128 + wm * 64 + mi * 16 + g;
        #pragma unroll
        for (int ni = 0; ni < 4; ni++) {
            int col = bn * 128 + wn * 32 + ni * 8 + 2 * T;
            float b0 = bias[col], b1 = bias[col + 1];
            #pragma unroll
            for (int hh = 0; hh < 2; hh++) {
                int rr = row0 + hh * 8;
                float v0 = acc[mi][ni][2*hh]   + b0;
                float v1 = acc[mi][ni][2*hh+1] + b1;
                if (GELU) { v0 = gelu_f(v0); v1 = gelu_f(v1); }
                if (RES) {
                    float2 rv = *(const float2*)(res + (size_t)rr * N + col);
                    v0 += rv.x; v1 += rv.y;
                }
                if (TFOUT) { v0 = f2tff(v0); v1 = f2tff(v1); }
                *(float2*)(C + (size_t)rr * N + col) = make_float2(v0, v1);
            }
        }
    }
}

// ============ flash attention: 4 warps x (32q x 64k), S tf32 / PV bf16 ====
// grid (S/128, B*H), 128 threads. smem 56KB: QF 32K, KF 16K, VF 8K.
// Each warp owns 32 query rows (m-atoms 2*wid, 2*wid+1): K/V fragments are
// reused across 2 mma -> block-level K/V smem traffic halved vs R11.
#define ATTN_SMEM ((8192 + 4096 + 2048) * 4)

__global__ void __launch_bounds__(128, 2) attn_kernel(
    const float* __restrict__ qkv, const __nv_bfloat16* __restrict__ vt16,
    float* __restrict__ o)
{
    extern __shared__ uint32_t sh[];
    uint32_t* QF = sh;            // [matom8][ks8][lane32][4]
    uint32_t* KF = sh + 8192;     // [na8][ks8][lane32][2]
    uint32_t* VF = sh + 12288;    // [na8][kt4][lane32][2] bf16x2

    int tid = threadIdx.x, lane = tid & 31, wid = tid >> 5;   // 4 warps
    int g = lane >> 2, T = lane & 3;
    int bh = blockIdx.y, b_ = bh / HH, h_ = bh % HH;
    int q0 = blockIdx.x * 128;
    size_t baseTok = (size_t)b_ * SS;

    int cg = tid & 15, ksq = cg >> 1, hfq = cg & 1;
    int sw = ksq & 3;
    int p0 = ((0 ^ sw) << 1), p1 = ((1 ^ sw) << 1),
        p2 = ((2 ^ sw) << 1), p3 = ((3 ^ sw) << 1);

    // ---- stage Q (pre-scaled by log2e/8 for exp2-domain softmax) ----
    const float QSCALE = 0.125f * 1.44269504088896340736f;
    #pragma unroll
    for (int i = 0; i < 16; i++) {
        int r = (tid >> 4) + i * 8;
        int wf = r >> 4, row = r & 15;
        int d = ((wf * 8 + ksq) * 32 + (row & 7) * 4) * 4 + (row >> 3) + 2 * hfq;
        float4 v = *(const float4*)(qkv + (baseTok + q0 + r) * NQKV + h_ * 64 + cg * 4);
        QF[d + (p0<<1)] = __float_as_uint(v.x * QSCALE);
        QF[d + (p1<<1)] = __float_as_uint(v.y * QSCALE);
        QF[d + (p2<<1)] = __float_as_uint(v.z * QSCALE);
        QF[d + (p3<<1)] = __float_as_uint(v.w * QSCALE);
    }

    // K staging geometry (8 float4 per thread per tile)
    int kD[8]; size_t kS[8];
    #pragma unroll
    for (int i = 0; i < 8; i++) {
        int key = (tid >> 4) + i * 8;
        kD[i] = (((key >> 3) * 8 + ksq) * 32 + (key & 7) * 4) * 2 + hfq;
        kS[i] = (baseTok + key) * NQKV + DD + h_ * 64 + cg * 4;
    }
    // V staging geometry: 2 (d,kt) slots per thread
    int vslot[2]; const __nv_bfloat16* vrow[2];
    #pragma unroll
    for (int j = 0; j < 2; j++) {
        int vd = tid >> 1, vkt = (tid & 1) * 2 + j;
        vslot[j] = (((vd >> 3) * 4 + vkt) * 32 + (vd & 7) * 4) * 2;
        vrow[j] = vt16 + ((size_t)bh * 64 + vd) * SS + vkt * 16;
    }

    float oacc[2][8][4];
    #pragma unroll
    for (int mi = 0; mi < 2; mi++)
        #pragma unroll
        for (int na = 0; na < 8; na++)
            #pragma unroll
            for (int r = 0; r < 4; r++) oacc[mi][na][r] = 0.0f;
    float m_[2][2], l_[2][2];
    #pragma unroll
    for (int mi = 0; mi < 2; mi++) {
        m_[mi][0] = -1e30f; m_[mi][1] = -1e30f;
        l_[mi][0] = 0.0f;   l_[mi][1] = 0.0f;
    }

    // prefetch first K/V tile
    float4 kreg[8]; uint4 vreg[2][2];
    #pragma unroll
    for (int i = 0; i < 8; i++) kreg[i] = *(const float4*)(qkv + kS[i]);
    #pragma unroll
    for (int j = 0; j < 2; j++) {
        vreg[j][0] = *(const uint4*)(vrow[j]);
        vreg[j][1] = *(const uint4*)(vrow[j] + 8);
    }

    for (int s0 = 0; s0 < SS; s0 += 64) {
        __syncthreads();   // prev-iter KF/VF readers done
        #pragma unroll
        for (int i = 0; i < 8; i++) {
            KF[kD[i]+p0] = __float_as_uint(kreg[i].x);
            KF[kD[i]+p1] = __float_as_uint(kreg[i].y);
            KF[kD[i]+p2] = __float_as_uint(kreg[i].z);
            KF[kD[i]+p3] = __float_as_uint(kreg[i].w);
        }
        #pragma unroll
        for (int j = 0; j < 2; j++) {
            const uint32_t* w1 = (const uint32_t*)&vreg[j][0];
            const uint32_t* w2 = (const uint32_t*)&vreg[j][1];
            #pragma unroll
            for (int Ti = 0; Ti < 4; Ti++)
                *(uint2*)&VF[vslot[j] + Ti * 2] = make_uint2(w1[Ti], w2[Ti]);
        }
        __syncthreads();
        if (s0 + 64 < SS) {
            #pragma unroll
            for (int i = 0; i < 8; i++)
                kreg[i] = *(const float4*)(qkv + kS[i] + (size_t)(s0 + 64) * NQKV);
            #pragma unroll
            for (int j = 0; j < 2; j++) {
                vreg[j][0] = *(const uint4*)(vrow[j] + s0 + 64);
                vreg[j][1] = *(const uint4*)(vrow[j] + s0 + 72);
            }
        }

        // S = Q @ K^T (tf32); each K fragment feeds 2 mma (mi=0,1)
        float sacc[2][8][4];
        #pragma unroll
        for (int mi = 0; mi < 2; mi++)
            #pragma unroll
            for (int na = 0; na < 8; na++)
                #pragma unroll
                for (int r = 0; r < 4; r++) sacc[mi][na][r] = 0.0f;
        #pragma unroll
        for (int ks = 0; ks < 8; ks++) {
            int lx = lane ^ (ks & 3);
            uint32_t qa0[4], qa1[4];
            *(uint4*)qa0 = *(const uint4*)&QF[(((wid * 2 + 0) * 8 + ks) * 32 + lx) * 4];
            *(uint4*)qa1 = *(const uint4*)&QF[(((wid * 2 + 1) * 8 + ks) * 32 + lx) * 4];
            #pragma unroll
            for (int na = 0; na < 8; na++) {
                uint32_t kb[2];
                *(uint2*)kb = *(const uint2*)&KF[((na * 8 + ks) * 32 + lx) * 2];
                mma8(sacc[0][na], qa0, kb);
                mma8(sacc[1][na], qa1, kb);
            }
        }

        // online softmax (exp2 domain); pack P into bf16 A-fragments
        uint32_t pregs[2][4][4];
        #pragma unroll
        for (int mi = 0; mi < 2; mi++) {
            float rm0 = -1e30f, rm1 = -1e30f;
            #pragma unroll
            for (int na = 0; na < 8; na++) {
                rm0 = fmaxf(rm0, fmaxf(sacc[mi][na][0], sacc[mi][na][1]));
                rm1 = fmaxf(rm1, fmaxf(sacc[mi][na][2], sacc[mi][na][3]));
            }
            rm0 = fmaxf(rm0, __shfl_xor_sync(0xffffffffu, rm0, 1));
            rm0 = fmaxf(rm0, __shfl_xor_sync(0xffffffffu, rm0, 2));
            rm1 = fmaxf(rm1, __shfl_xor_sync(0xffffffffu, rm1, 1));
            rm1 = fmaxf(rm1, __shfl_xor_sync(0xffffffffu, rm1, 2));
            float mn0 = fmaxf(m_[mi][0], rm0), mn1 = fmaxf(m_[mi][1], rm1);
            float al0 = exp2f(m_[mi][0] - mn0), al1 = exp2f(m_[mi][1] - mn1);
            m_[mi][0] = mn0; m_[mi][1] = mn1;
            float rs0 = 0.0f, rs1 = 0.0f;
            #pragma unroll
            for (int na = 0; na < 8; na++) {
                float e0 = exp2f(sacc[mi][na][0] - mn0);
                float e1 = exp2f(sacc[mi][na][1] - mn0);
                float e2 = exp2f(sacc[mi][na][2] - mn1);
                float e3 = exp2f(sacc[mi][na][3] - mn1);
                rs0 += e0 + e1; rs1 += e2 + e3;
                int kt = na >> 1;
                if ((na & 1) == 0) {
                    pregs[mi][kt][0] = packbf(e0, e1);
                    pregs[mi][kt][1] = packbf(e2, e3);
                } else {
                    pregs[mi][kt][2] = packbf(e0, e1);
                    pregs[mi][kt][3] = packbf(e2, e3);
                }
            }
            rs0 += __shfl_xor_sync(0xffffffffu, rs0, 1);
            rs0 += __shfl_xor_sync(0xffffffffu, rs0, 2);
            rs1 += __shfl_xor_sync(0xffffffffu, rs1, 1);
            rs1 += __shfl_xor_sync(0xffffffffu, rs1, 2);
            l_[mi][0] = l_[mi][0] * al0 + rs0;
            l_[mi][1] = l_[mi][1] * al1 + rs1;
            #pragma unroll
            for (int na = 0; na < 8; na++) {
                oacc[mi][na][0] *= al0; oacc[mi][na][1] *= al0;
                oacc[mi][na][2] *= al1; oacc[mi][na][3] *= al1;
            }
        }

        // O += P @ V (bf16); each V fragment feeds 2 mma (mi=0,1)
        #pragma unroll
        for (int kt = 0; kt < 4; kt++) {
            #pragma unroll
            for (int na = 0; na < 8; na++) {
                uint32_t vb[2];
                *(uint2*)vb = *(const uint2*)&VF[((na * 4 + kt) * 32 + lane) * 2];
                mma16bf(oacc[0][na], pregs[0][kt], vb);
                mma16bf(oacc[1][na], pregs[1][kt], vb);
            }
        }
    }

    // epilogue (tf32-rounded: feeds O-proj GEMM)
    #pragma unroll
    for (int mi = 0; mi < 2; mi++) {
        float inv0 = 1.0f / l_[mi][0], inv1 = 1.0f / l_[mi][1];
        int row0 = q0 + wid * 32 + mi * 16 + g;
        #pragma unroll
        for (int na = 0; na < 8; na++) {
            int col = h_ * 64 + na * 8 + 2 * T;
            *(float2*)(o + (baseTok + row0)     * DD + col) =
                make_float2(f2tff(oacc[mi][na][0] * inv0), f2tff(oacc[mi][na][1] * inv0));
            *(float2*)(o + (baseTok + row0 + 8) * DD + col) =
                make_float2(f2tff(oacc[mi][na][2] * inv1), f2tff(oacc[mi][na][3] * inv1));
        }
    }
}

// ---------------- launch ---------------------------------------------------
extern "C" void kernel_launch(void* const* d_in, const int* in_sizes, int n_in,
                              void* d_out, int out_size)
{
    (void)in_sizes; (void)n_in; (void)out_size;
    const float* x    = (const float*)d_in[0];
    const float* wq_w = (const float*)d_in[1];
    const float* wq_b = (const float*)d_in[2];
    const float* wk_w = (const float*)d_in[3];
    const float* wk_b = (const float*)d_in[4];
    const float* wv_w = (const float*)d_in[5];
    const float* wv_b = (const float*)d_in[6];
    const float* wo_w = (const float*)d_in[7];
    const float* wo_b = (const float*)d_in[8];
    const float* ln_g = (const float*)d_in[9];
    const float* ln_b = (const float*)d_in[10];
    const float* w1   = (const float*)d_in[11];
    const float* b1   = (const float*)d_in[12];
    const float* w2   = (const float*)d_in[13];
    const float* b2   = (const float*)d_in[14];
    float* out = (float*)d_out;

    float *h, *qkv, *o, *y, *z, *u, *wtq, *btq, *wto, *wt1, *wt2;
    __nv_bfloat16* vt16;
    cudaGetSymbolAddress((void**)&h,    g_h);
    cudaGetSymbolAddress((void**)&qkv,  g_qkv);
    cudaGetSymbolAddress((void**)&vt16, g_vt16);
    cudaGetSymbolAddress((void**)&o,    g_o);
    cudaGetSymbolAddress((void**)&y,    g_y);
    cudaGetSymbolAddress((void**)&z,    g_z);
    cudaGetSymbolAddress((void**)&u,    g_u);
    cudaGetSymbolAddress((void**)&wtq,  g_wtq);
    cudaGetSymbolAddress((void**)&btq,  g_btq);
    cudaGetSymbolAddress((void**)&wto,  g_wto);
    cudaGetSymbolAddress((void**)&wt1,  g_wt1);
    cudaGetSymbolAddress((void**)&wt2,  g_wt2);

    cudaFuncSetAttribute(tc_gemm<false, false, true >, cudaFuncAttributeMaxDynamicSharedMemorySize, GEMM_SMEM);
    cudaFuncSetAttribute(tc_gemm<false, true,  false>, cudaFuncAttributeMaxDynamicSharedMemorySize, GEMM_SMEM);
    cudaFuncSetAttribute(tc_gemm<true,  false, true >, cudaFuncAttributeMaxDynamicSharedMemorySize, GEMM_SMEM);
    cudaFuncSetAttribute(attn_kernel, cudaFuncAttributeMaxDynamicSharedMemorySize, ATTN_SMEM);

    // 0) weight prep
    prep_w_kernel<<<6912, dim3(32, 8)>>>(wq_w, wk_w, wv_w, wo_w, w1, w2,
                                         wtq, wto, wt1, wt2);
    // 1) qkv bias pack
    qkv_bias_kernel<<<3, 256>>>(wq_b, wk_b, wv_b, btq);

    // 2) LN1 (tf32 out)
    ln_kernel<<<MM, 256>>>(x, ln_g, ln_b, h);

    // 3) fused QKV projection (tf32 out)  [capture slot 3 -> ncu]
    tc_gemm<false, false, true><<<dim3(NQKV/128, MM/128), 256, GEMM_SMEM>>>(h, wtq, btq, nullptr, qkv, NQKV, DD);

    // 4) V transpose+bf16 pack
    vtrans_kernel<<<dim3(SS/32, 2, BB*HH), dim3(32, 8)>>>(qkv, vt16);

    // 5) attention
    attn_kernel<<<dim3(SS/128, BB*HH), 128, ATTN_SMEM>>>(qkv, vt16, o);

    // 6) O-proj + bias + residual(x) -> fp32 y
    tc_gemm<false, true, false><<<dim3(DD/128, MM/128), 256, GEMM_SMEM>>>(o, wto, wo_b, x, y, DD, DD);

    // 7) LN2 (tf32 out)
    ln_kernel<<<MM, 256>>>(y, ln_g, ln_b, z);

    // 8) FFN1 + bias + exact GELU (tf32 out)
    tc_gemm<true, false, true><<<dim3(FF/128, MM/128), 256, GEMM_SMEM>>>(z, wt1, b1, nullptr, u, FF, DD);

    // 9) FFN2 + bias + residual(y) -> out (fp32)
    tc_gemm<false, true, false><<<dim3(DD/128, MM/128), 256, GEMM_SMEM>>>(u, wt2, b2, y, out, DD, FF);
}

// round 14
// speedup vs baseline: 1.4991x; 1.4991x over previous
#include <cuda_runtime.h>
#include <cuda_bf16.h>
#include <math.h>
#include <cstdint>

// ---------------- problem dims (fixed) ----------------
#define BB   2
#define SS   2048
#define DD   768
#define HH   12
#define DK   64
#define FF   3072
#define MM   (BB*SS)          // 4096 tokens
#define NQKV (3*DD)           // 2304 fused QKV cols

// ---------------- scratch (device globals; allocation-free) ----------------
__device__ float g_h[MM*DD];            // LN1 output (tf32-rounded)
__device__ float g_qkv[MM*NQKV];        // fused QKV [M, 2304] (tf32-rounded)
__device__ __nv_bfloat16 g_vt16[BB*HH*DK*SS]; // V transposed [bh][d][s], bf16
__device__ float g_o[MM*DD];            // attn output (tf32-rounded)
__device__ float g_y[MM*DD];            // after O-proj + residual (fp32)
__device__ float g_z[MM*DD];            // LN2 output (tf32-rounded)
__device__ float g_u[MM*FF];            // FFN hidden (tf32-rounded)
__device__ float g_wtq[NQKV*DD];        // fused QKV weights^T (tf32)
__device__ float g_btq[NQKV];           // fused QKV bias
__device__ float g_wto[DD*DD];          // wo^T (tf32)
__device__ float g_wt1[FF*DD];          // w1^T (tf32)
__device__ float g_wt2[DD*FF];          // w2^T (tf32)

// ================= helpers =================
__device__ __forceinline__ uint32_t f2tf(float f) {
    uint32_t u; asm("cvt.rna.tf32.f32 %0, %1;" : "=r"(u) : "f"(f)); return u;
}
__device__ __forceinline__ float f2tff(float f) { return __uint_as_float(f2tf(f)); }
__device__ __forceinline__ void mma8(float* c, const uint32_t* a, const uint32_t* b) {
    asm volatile("mma.sync.aligned.m16n8k8.row.col.f32.tf32.tf32.f32 "
        "{%0,%1,%2,%3}, {%4,%5,%6,%7}, {%8,%9}, {%0,%1,%2,%3};"
        : "+f"(c[0]), "+f"(c[1]), "+f"(c[2]), "+f"(c[3])
        : "r"(a[0]), "r"(a[1]), "r"(a[2]), "r"(a[3]), "r"(b[0]), "r"(b[1]));
}
__device__ __forceinline__ void mma16bf(float* c, const uint32_t* a, const uint32_t* b) {
    asm volatile("mma.sync.aligned.m16n8k16.row.col.f32.bf16.bf16.f32 "
        "{%0,%1,%2,%3}, {%4,%5,%6,%7}, {%8,%9}, {%0,%1,%2,%3};"
        : "+f"(c[0]), "+f"(c[1]), "+f"(c[2]), "+f"(c[3])
        : "r"(a[0]), "r"(a[1]), "r"(a[2]), "r"(a[3]), "r"(b[0]), "r"(b[1]));
}
// pack: lo -> bits[15:0], hi -> bits[31:16]
__device__ __forceinline__ uint32_t packbf(float lo, float hi) {
    uint32_t d;
    asm("cvt.rn.bf16x2.f32 %0, %1, %2;" : "=r"(d) : "f"(hi), "f"(lo));
    return d;
}
__device__ __forceinline__ float gelu_f(float v) {
    return 0.5f * v * (1.0f + erff(v * 0.70710678118654752f));
}
__device__ __forceinline__ float f4e(const float4& v, int j) {
    return ((const float*)&v)[j];
}

// ---------------- LayerNorm: one block per row, tf32-rounded output -------
__global__ void __launch_bounds__(256) ln_kernel(
    const float* __restrict__ x, const float* __restrict__ gw,
    const float* __restrict__ bw, float* __restrict__ out)
{
    __shared__ float red[8];
    int row = blockIdx.x;
    int tid = threadIdx.x;
    const float* xr = x + (size_t)row * DD;

    float v0 = xr[tid], v1 = xr[tid + 256], v2 = xr[tid + 512];
    float s = v0 + v1 + v2;
    #pragma unroll
    for (int o = 16; o > 0; o >>= 1) s += __shfl_xor_sync(0xffffffffu, s, o);
    if ((tid & 31) == 0) red[tid >> 5] = s;
    __syncthreads();
    float tot = red[0]+red[1]+red[2]+red[3]+red[4]+red[5]+red[6]+red[7];
    float mu = tot * (1.0f / 768.0f);
    float d0 = v0 - mu, d1 = v1 - mu, d2 = v2 - mu;
    float q = d0*d0 + d1*d1 + d2*d2;
    #pragma unroll
    for (int o = 16; o > 0; o >>= 1) q += __shfl_xor_sync(0xffffffffu, q, o);
    __syncthreads();
    if ((tid & 31) == 0) red[tid >> 5] = q;
    __syncthreads();
    float vtot = red[0]+red[1]+red[2]+red[3]+red[4]+red[5]+red[6]+red[7];
    float rstd = rsqrtf(vtot * (1.0f / 768.0f) + 1e-5f);
    float* orow = out + (size_t)row * DD;
    orow[tid]       = f2tff(d0 * rstd * gw[tid]       + bw[tid]);
    orow[tid + 256] = f2tff(d1 * rstd * gw[tid + 256] + bw[tid + 256]);
    orow[tid + 512] = f2tff(d2 * rstd * gw[tid + 512] + bw[tid + 512]);
}

// ---------------- weight prep: transposes + packs (tf32) ------------------
__device__ __forceinline__ void trans_tile(
    const float* __restrict__ W, float* __restrict__ Wt, int K, int N,
    int bx, int by, float t[32][33], int tx, int ty)
{
    #pragma unroll
    for (int l = 0; l < 4; l++) {
        int k = by * 32 + ty + l * 8;
        t[ty + l * 8][tx] = W[(size_t)k * N + bx * 32 + tx];
    }
    __syncthreads();
    #pragma unroll
    for (int l = 0; l < 4; l++) {
        int n = bx * 32 + ty + l * 8;
        Wt[(size_t)n * K + by * 32 + tx] = f2tff(t[tx][ty + l * 8]);
    }
}

// grid: 1728 (qkv) + 576 (wo) + 2304 (w1) + 2304 (w2) = 6912
__global__ void __launch_bounds__(256) prep_w_kernel(
    const float* __restrict__ wq, const float* __restrict__ wk,
    const float* __restrict__ wv, const float* __restrict__ wo,
    const float* __restrict__ w1, const float* __restrict__ w2,
    float* __restrict__ wtq, float* __restrict__ wto,
    float* __restrict__ wt1, float* __restrict__ wt2)
{
    __shared__ float t[32][33];
    int id = blockIdx.x;
    int tx = threadIdx.x, ty = threadIdx.y;
    if (id < 1728) {
        int p = id / 576, rem = id % 576;
        int bx = rem % 24, by = rem / 24;
        const float* wp = (p == 0) ? wq : (p == 1) ? wk : wv;
        int np0 = bx * 32, d0 = by * 32;
        int hh = np0 >> 6, kk0 = np0 & 63;
        #pragma unroll
        for (int l = 0; l < 4; l++) {
            int d = d0 + ty + l * 8;
            t[ty + l * 8][tx] = wp[((size_t)hh * DD + d) * DK + kk0 + tx];
        }
        __syncthreads();
        #pragma unroll
        for (int l = 0; l < 4; l++) {
            int n = np0 + ty + l * 8;
            wtq[((size_t)p * DD + n) * DD + d0 + tx] = f2tff(t[tx][ty + l * 8]);
        }
    } else if (id < 2304) {
        int rem = id - 1728;
        trans_tile(wo, wto, DD, DD, rem % 24, rem / 24, t, tx, ty);
    } else if (id < 4608) {
        int rem = id - 2304;
        trans_tile(w1, wt1, DD, FF, rem % 96, rem / 96, t, tx, ty);
    } else {
        int rem = id - 4608;
        trans_tile(w2, wt2, FF, DD, rem % 24, rem / 24, t, tx, ty);
    }
}

__global__ void qkv_bias_kernel(
    const float* __restrict__ bq, const float* __restrict__ bk,
    const float* __restrict__ bv, float* __restrict__ bt)
{
    int i = blockIdx.x * 256 + threadIdx.x;   // grid 3, 256 thr: covers 768
    if (i < DD) { bt[i] = bq[i]; bt[DD + i] = bk[i]; bt[2 * DD + i] = bv[i]; }
}

// ---------------- V transpose: qkv V-part -> vt16[bh][d][s] bf16 ----------
__global__ void __launch_bounds__(256) vtrans_kernel(
    const float* __restrict__ qkv, __nv_bfloat16* __restrict__ vt16)
{
    __shared__ float t[32][33];
    int s0 = blockIdx.x * 32;
    int d0 = blockIdx.y * 32;
    int bh = blockIdx.z;
    int b_ = bh / HH, h_ = bh % HH;
    int tx = threadIdx.x, ty = threadIdx.y;
    #pragma unroll
    for (int l = 0; l < 4; l++) {
        int s = s0 + ty + l * 8;
        t[ty + l * 8][tx] = qkv[((size_t)(b_ * SS + s)) * NQKV + 2 * DD + h_ * 64 + d0 + tx];
    }
    __syncthreads();
    if (tx < 16) {
        #pragma unroll
        for (int l = 0; l < 4; l++) {
            int d = d0 + ty + l * 8;
            uint32_t w = packbf(t[2 * tx][ty + l * 8], t[2 * tx + 1][ty + l * 8]);
            uint32_t* orow = (uint32_t*)(vt16 + ((size_t)bh * 64 + d) * SS + s0);
            orow[tx] = w;
        }
    }
}

// ============ TF32 mma.sync GEMM: C[M,N] = A[M,K] @ Bt[N,K]^T =============
// Block 128x128, BK=32, 256 threads = 8 warps (2m x 4n), warp tile 64x32.
// Fragment layouts identical to R11; staging re-mapped so each thread owns
// full uint4 (A) / uint2 (B) slots -> 4 STS.128 + 8 STS.64 (was 32 STS.32).
#define GEMM_SMEM (16384 * 4)

template<bool GELU, bool RES, bool TFOUT>
__global__ void __launch_bounds__(256, 2) tc_gemm(
    const float* __restrict__ A, const float* __restrict__ Bt,
    const float* __restrict__ bias, const float* __restrict__ res,
    float* __restrict__ C, int N, int K)
{
    extern __shared__ uint32_t sh[];
    uint32_t* sA = sh;          // [2][4096]
    uint32_t* sB = sh + 8192;   // [2][4096]
    int tid = threadIdx.x, lane = tid & 31, wid = tid >> 5;
    int wm = wid & 1, wn = wid >> 1;
    int bm = blockIdx.y, bn = blockIdx.x;

    const float* Ag = A  + (size_t)(bm * 128) * K;
    const float* Bg = Bt + (size_t)(bn * 128) * K;

    // A staging: thread -> (ma, row0, ksv); owns rows ma*16+row0, +8; 8 k.
    int ma = tid >> 5, row0 = (tid >> 2) & 7, ksv = tid & 3;
    const float* aG0 = Ag + (size_t)(ma * 16 + row0) * K + ksv * 8;
    const float* aG1 = aG0 + (size_t)8 * K;
    int aBase = (((ma * 4 + ksv) * 32) + row0 * 4) * 4;   // + q*4
    // B staging: thread -> (na, nn0 pair, ksv); rows na*8+nn0, +1; 8 k.
    int na = tid >> 4, nn0 = ((tid >> 2) & 3) * 2;
    const float* bG0 = Bg + (size_t)(na * 8 + nn0) * K + ksv * 8;
    const float* bG1 = bG0 + (size_t)K;
    int bBase0 = (((na * 4 + ksv) * 32) + nn0 * 4) * 2;   // + q*2
    int bBase1 = bBase0 + 8;                               // (nn0+1) slot

    float acc[4][4][4];
    #pragma unroll
    for (int mi = 0; mi < 4; mi++)
        #pragma unroll
        for (int ni = 0; ni < 4; ni++)
            #pragma unroll
            for (int r = 0; r < 4; r++) acc[mi][ni][r] = 0.0f;

    // ---- stage chunk 0 ----
    {
        float4 a0 = *(const float4*)(aG0), a1 = *(const float4*)(aG0 + 4);
        float4 a2 = *(const float4*)(aG1), a3 = *(const float4*)(aG1 + 4);
        float4 b0 = *(const float4*)(bG0), b1 = *(const float4*)(bG0 + 4);
        float4 b2 = *(const float4*)(bG1), b3 = *(const float4*)(bG1 + 4);
        #pragma unroll
        for (int j = 0; j < 4; j++) {
            int q = j ^ ksv;
            *(float4*)&sA[aBase + q * 4] =
                make_float4(f4e(a0,j), f4e(a2,j), f4e(a1,j), f4e(a3,j));
            *(float2*)&sB[bBase0 + q * 2] = make_float2(f4e(b0,j), f4e(b1,j));
            *(float2*)&sB[bBase1 + q * 2] = make_float2(f4e(b2,j), f4e(b3,j));
        }
    }
    __syncthreads();

    int NT = K >> 5;
    for (int t = 0; t < NT; t++) {
        float4 pa[4], pb[4];
        bool pf = (t + 1 < NT);
        if (pf) {
            int k0 = (t + 1) * 32;
            pa[0] = *(const float4*)(aG0 + k0); pa[1] = *(const float4*)(aG0 + k0 + 4);
            pa[2] = *(const float4*)(aG1 + k0); pa[3] = *(const float4*)(aG1 + k0 + 4);
            pb[0] = *(const float4*)(bG0 + k0); pb[1] = *(const float4*)(bG0 + k0 + 4);
            pb[2] = *(const float4*)(bG1 + k0); pb[3] = *(const float4*)(bG1 + k0 + 4);
        }
        const uint32_t* cA = sA + (t & 1) * 4096;
        const uint32_t* cB = sB + (t & 1) * 4096;
        #pragma unroll
        for (int ks = 0; ks < 4; ks++) {
            int lx = lane ^ ks;
            uint32_t ua[4][4], ub[4][2];
            #pragma unroll
            for (int mi = 0; mi < 4; mi++)
                *(uint4*)ua[mi] = *(const uint4*)&cA[(((wm*4+mi)*4 + ks)*32 + lx)*4];
            #pragma unroll
            for (int ni = 0; ni < 4; ni++)
                *(uint2*)ub[ni] = *(const uint2*)&cB[(((wn*4+ni)*4 + ks)*32 + lx)*2];
            #pragma unroll
            for (int mi = 0; mi < 4; mi++)
                #pragma unroll
                for (int ni = 0; ni < 4; ni++)
                    mma8(acc[mi][ni], ua[mi], ub[ni]);
        }
        if (pf) {
            uint32_t* nA = sA + ((t + 1) & 1) * 4096;
            uint32_t* nB = sB + ((t + 1) & 1) * 4096;
            #pragma unroll
            for (int j = 0; j < 4; j++) {
                int q = j ^ ksv;
                *(float4*)&nA[aBase + q * 4] =
                    make_float4(f4e(pa[0],j), f4e(pa[2],j), f4e(pa[1],j), f4e(pa[3],j));
                *(float2*)&nB[bBase0 + q * 2] = make_float2(f4e(pb[0],j), f4e(pb[1],j));
                *(float2*)&nB[bBase1 + q * 2] = make_float2(f4e(pb[2],j), f4e(pb[3],j));
            }
        }
        __syncthreads();
    }

    int g = lane >> 2, T = lane & 3;
    #pragma unroll
    for (int mi = 0; mi < 4; mi++) {
        int row0e = bm * 128 + wm * 64 + mi * 16 + g;
        #pragma unroll
        for (int ni = 0; ni < 4; ni++) {
            int col = bn * 128 + wn * 32 + ni * 8 + 2 * T;
            float b0 = bias[col], b1 = bias[col + 1];
            #pragma unroll
            for (int hh = 0; hh < 2; hh++) {
                int rr = row0e + hh * 8;
                float v0 = acc[mi][ni][2*hh]   + b0;
                float v1 = acc[mi][ni][2*hh+1] + b1;
                if (GELU) { v0 = gelu_f(v0); v1 = gelu_f(v1); }
                if (RES) {
                    float2 rv = *(const float2*)(res + (size_t)rr * N + col);
                    v0 += rv.x; v1 += rv.y;
                }
                if (TFOUT) { v0 = f2tff(v0); v1 = f2tff(v1); }
                *(float2*)(C + (size_t)rr * N + col) = make_float2(v0, v1);
            }
        }
    }
}

// ============ flash attention (R11 structure: 8 warps x 16q) ==============
// grid (S/128, B*H), 256 threads. smem 56KB: QF 32K, KF 16K, VF 8K.
// S = QK^T in tf32; P packed to bf16 in regs; PV in bf16 m16n8k16.
#define ATTN_SMEM ((8192 + 4096 + 2048) * 4)

__global__ void __launch_bounds__(256, 2) attn_kernel(
    const float* __restrict__ qkv, const __nv_bfloat16* __restrict__ vt16,
    float* __restrict__ o)
{
    extern __shared__ uint32_t sh[];
    uint32_t* QF = sh;            // [warp8][ks8][lane32][4]
    uint32_t* KF = sh + 8192;     // [na8][ks8][lane32][2]
    uint32_t* VF = sh + 12288;    // [na8][kt4][lane32][2] bf16x2

    int tid = threadIdx.x, lane = tid & 31, wid = tid >> 5;
    int g = lane >> 2, T = lane & 3;
    int bh = blockIdx.y, b_ = bh / HH, h_ = bh % HH;
    int q0 = blockIdx.x * 128;
    size_t baseTok = (size_t)b_ * SS;

    int cg = tid & 15, ksq = cg >> 1, hfq = cg & 1;
    int sw = ksq & 3;
    int p0 = ((0 ^ sw) << 1), p1 = ((1 ^ sw) << 1),
        p2 = ((2 ^ sw) << 1), p3 = ((3 ^ sw) << 1);

    // ---- stage Q (pre-scaled by log2e/8: exp2-domain softmax) ----
    const float QSCALE = 0.125f * 1.44269504088896340736f;
    #pragma unroll
    for (int i = 0; i < 8; i++) {
        int r = (tid >> 4) + i * 16;
        int wf = r >> 4, row = r & 15;
        int d = ((wf * 8 + ksq) * 32 + (row & 7) * 4) * 4 + (row >> 3) + 2 * hfq;
        float4 v = *(const float4*)(qkv + (baseTok + q0 + r) * NQKV + h_ * 64 + cg * 4);
        QF[d + (p0<<1)] = __float_as_uint(v.x * QSCALE);
        QF[d + (p1<<1)] = __float_as_uint(v.y * QSCALE);
        QF[d + (p2<<1)] = __float_as_uint(v.z * QSCALE);
        QF[d + (p3<<1)] = __float_as_uint(v.w * QSCALE);
    }

    // K staging geometry
    int kD[4]; size_t kS[4];
    #pragma unroll
    for (int i = 0; i < 4; i++) {
        int key = (tid >> 4) + i * 16;
        kD[i] = (((key >> 3) * 8 + ksq) * 32 + (key & 7) * 4) * 2 + hfq;
        kS[i] = (baseTok + key) * NQKV + DD + h_ * 64 + cg * 4;
    }
    // V staging geometry (bf16 b-frag): thread -> (d, kt)
    int vd = tid >> 2, vkt = tid & 3;
    int vslot = (((vd >> 3) * 4 + vkt) * 32 + (vd & 7) * 4) * 2;
    const __nv_bfloat16* vrow = vt16 + ((size_t)bh * 64 + vd) * SS + vkt * 16;

    float oacc[8][4];
    #pragma unroll
    for (int na = 0; na < 8; na++)
        #pragma unroll
        for (int r = 0; r < 4; r++) oacc[na][r] = 0.0f;
    float m0 = -1e30f, m1 = -1e30f, l0 = 0.0f, l1 = 0.0f;

    // prefetch first K/V tile
    float4 kreg[4]; uint4 vreg[2];
    #pragma unroll
    for (int i = 0; i < 4; i++) kreg[i] = *(const float4*)(qkv + kS[i]);
    vreg[0] = *(const uint4*)(vrow);
    vreg[1] = *(const uint4*)(vrow + 8);

    for (int s0 = 0; s0 < SS; s0 += 64) {
        __syncthreads();
        #pragma unroll
        for (int i = 0; i < 4; i++) {
            KF[kD[i]+p0] = __float_as_uint(kreg[i].x);
            KF[kD[i]+p1] = __float_as_uint(kreg[i].y);
            KF[kD[i]+p2] = __float_as_uint(kreg[i].z);
            KF[kD[i]+p3] = __float_as_uint(kreg[i].w);
        }
        {
            const uint32_t* w1 = (const uint32_t*)&vreg[0];
            const uint32_t* w2 = (const uint32_t*)&vreg[1];
            #pragma unroll
            for (int Ti = 0; Ti < 4; Ti++)
                *(uint2*)&VF[vslot + Ti * 2] = make_uint2(w1[Ti], w2[Ti]);
        }
        __syncthreads();
        if (s0 + 64 < SS) {
            #pragma unroll
            for (int i = 0; i < 4; i++)
                kreg[i] = *(const float4*)(qkv + kS[i] + (size_t)(s0 + 64) * NQKV);
            vreg[0] = *(const uint4*)(vrow + s0 + 64);
            vreg[1] = *(const uint4*)(vrow + s0 + 72);
        }

        // S = Q @ K^T (tf32)
        float sacc[8][4];
        #pragma unroll
        for (int na = 0; na < 8; na++)
            #pragma unroll
            for (int r = 0; r < 4; r++) sacc[na][r] = 0.0f;
        #pragma unroll
        for (int ks = 0; ks < 8; ks++) {
            int lx = lane ^ (ks & 3);
            uint32_t qa[4];
            *(uint4*)qa = *(const uint4*)&QF[((wid * 8 + ks) * 32 + lx) * 4];
            #pragma unroll
            for (int na = 0; na < 8; na++) {
                uint32_t kb[2];
                *(uint2*)kb = *(const uint2*)&KF[((na * 8 + ks) * 32 + lx) * 2];
                mma8(sacc[na], qa, kb);
            }
        }

        // online softmax (exp2 domain); pack P into bf16 A-fragments
        float rm0 = -1e30f, rm1 = -1e30f;
        #pragma unroll
        for (int na = 0; na < 8; na++) {
            rm0 = fmaxf(rm0, fmaxf(sacc[na][0], sacc[na][1]));
            rm1 = fmaxf(rm1, fmaxf(sacc[na][2], sacc[na][3]));
        }
        rm0 = fmaxf(rm0, __shfl_xor_sync(0xffffffffu, rm0, 1));
        rm0 = fmaxf(rm0, __shfl_xor_sync(0xffffffffu, rm0, 2));
        rm1 = fmaxf(rm1, __shfl_xor_sync(0xffffffffu, rm1, 1));
        rm1 = fmaxf(rm1, __shfl_xor_sync(0xffffffffu, rm1, 2));
        float mn0 = fmaxf(m0, rm0), mn1 = fmaxf(m1, rm1);
        float al0 = exp2f(m0 - mn0), al1 = exp2f(m1 - mn1);
        m0 = mn0; m1 = mn1;
        float rs0 = 0.0f, rs1 = 0.0f;
        uint32_t pregs[4][4];
        #pragma unroll
        for (int na = 0; na < 8; na++) {
            float e0 = exp2f(sacc[na][0] - mn0);
            float e1 = exp2f(sacc[na][1] - mn0);
            float e2 = exp2f(sacc[na][2] - mn1);
            float e3 = exp2f(sacc[na][3] - mn1);
            rs0 += e0 + e1; rs1 += e2 + e3;
            int kt = na >> 1;
            if ((na & 1) == 0) {
                pregs[kt][0] = packbf(e0, e1);
                pregs[kt][1] = packbf(e2, e3);
            } else {
                pregs[kt][2] = packbf(e0, e1);
                pregs[kt][3] = packbf(e2, e3);
            }
        }
        rs0 += __shfl_xor_sync(0xffffffffu, rs0, 1);
        rs0 += __shfl_xor_sync(0xffffffffu, rs0, 2);
        rs1 += __shfl_xor_sync(0xffffffffu, rs1, 1);
        rs1 += __shfl_xor_sync(0xffffffffu, rs1, 2);
        l0 = l0 * al0 + rs0; l1 = l1 * al1 + rs1;
        #pragma unroll
        for (int na = 0; na < 8; na++) {
            oacc[na][0] *= al0; oacc[na][1] *= al0;
            oacc[na][2] *= al1; oacc[na][3] *= al1;
        }

        // O += P @ V (bf16 m16n8k16)
        #pragma unroll
        for (int kt = 0; kt < 4; kt++) {
            #pragma unroll
            for (int na = 0; na < 8; na++) {
                uint32_t vb[2];
                *(uint2*)vb = *(const uint2*)&VF[((na * 4 + kt) * 32 + lane) * 2];
                mma16bf(oacc[na], pregs[kt], vb);
            }
        }
    }

    // epilogue (tf32-rounded: feeds O-proj GEMM)
    float inv0 = 1.0f / l0, inv1 = 1.0f / l1;
    int row0 = q0 + wid * 16 + g;
    #pragma unroll
    for (int na = 0; na < 8; na++) {
        int col = h_ * 64 + na * 8 + 2 * T;
        *(float2*)(o + (baseTok + row0)     * DD + col) =
            make_float2(f2tff(oacc[na][0] * inv0), f2tff(oacc[na][1] * inv0));
        *(float2*)(o + (baseTok + row0 + 8) * DD + col) =
            make_float2(f2tff(oacc[na][2] * inv1), f2tff(oacc[na][3] * inv1));
    }
}

// ---------------- launch ---------------------------------------------------
extern "C" void kernel_launch(void* const* d_in, const int* in_sizes, int n_in,
                              void* d_out, int out_size)
{
    (void)in_sizes; (void)n_in; (void)out_size;
    const float* x    = (const float*)d_in[0];
    const float* wq_w = (const float*)d_in[1];
    const float* wq_b = (const float*)d_in[2];
    const float* wk_w = (const float*)d_in[3];
    const float* wk_b = (const float*)d_in[4];
    const float* wv_w = (const float*)d_in[5];
    const float* wv_b = (const float*)d_in[6];
    const float* wo_w = (const float*)d_in[7];
    const float* wo_b = (const float*)d_in[8];
    const float* ln_g = (const float*)d_in[9];
    const float* ln_b = (const float*)d_in[10];
    const float* w1   = (const float*)d_in[11];
    const float* b1   = (const float*)d_in[12];
    const float* w2   = (const float*)d_in[13];
    const float* b2   = (const float*)d_in[14];
    float* out = (float*)d_out;

    float *h, *qkv, *o, *y, *z, *u, *wtq, *btq, *wto, *wt1, *wt2;
    __nv_bfloat16* vt16;
    cudaGetSymbolAddress((void**)&h,    g_h);
    cudaGetSymbolAddress((void**)&qkv,  g_qkv);
    cudaGetSymbolAddress((void**)&vt16, g_vt16);
    cudaGetSymbolAddress((void**)&o,    g_o);
    cudaGetSymbolAddress((void**)&y,    g_y);
    cudaGetSymbolAddress((void**)&z,    g_z);
    cudaGetSymbolAddress((void**)&u,    g_u);
    cudaGetSymbolAddress((void**)&wtq,  g_wtq);
    cudaGetSymbolAddress((void**)&btq,  g_btq);
    cudaGetSymbolAddress((void**)&wto,  g_wto);
    cudaGetSymbolAddress((void**)&wt1,  g_wt1);
    cudaGetSymbolAddress((void**)&wt2,  g_wt2);

    cudaFuncSetAttribute(tc_gemm<false, false, true >, cudaFuncAttributeMaxDynamicSharedMemorySize, GEMM_SMEM);
    cudaFuncSetAttribute(tc_gemm<false, true,  false>, cudaFuncAttributeMaxDynamicSharedMemorySize, GEMM_SMEM);
    cudaFuncSetAttribute(tc_gemm<true,  false, true >, cudaFuncAttributeMaxDynamicSharedMemorySize, GEMM_SMEM);
    cudaFuncSetAttribute(attn_kernel, cudaFuncAttributeMaxDynamicSharedMemorySize, ATTN_SMEM);

    // 0) weight prep
    prep_w_kernel<<<6912, dim3(32, 8)>>>(wq_w, wk_w, wv_w, wo_w, w1, w2,
                                         wtq, wto, wt1, wt2);
    // 1) qkv bias pack
    qkv_bias_kernel<<<3, 256>>>(wq_b, wk_b, wv_b, btq);

    // 2) LN1 (tf32 out)
    ln_kernel<<<MM, 256>>>(x, ln_g, ln_b, h);

    // 3) fused QKV projection (tf32 out)  [capture slot 3 -> ncu]
    tc_gemm<false, false, true><<<dim3(NQKV/128, MM/128), 256, GEMM_SMEM>>>(h, wtq, btq, nullptr, qkv, NQKV, DD);

    // 4) V transpose+bf16 pack
    vtrans_kernel<<<dim3(SS/32, 2, BB*HH), dim3(32, 8)>>>(qkv, vt16);

    // 5) attention (R11 structure)
    attn_kernel<<<dim3(SS/128, BB*HH), 256, ATTN_SMEM>>>(qkv, vt16, o);

    // 6) O-proj + bias + residual(x) -> fp32 y
    tc_gemm<false, true, false><<<dim3(DD/128, MM/128), 256, GEMM_SMEM>>>(o, wto, wo_b, x, y, DD, DD);

    // 7) LN2 (tf32 out)
    ln_kernel<<<MM, 256>>>(y, ln_g, ln_b, z);

    // 8) FFN1 + bias + exact GELU (tf32 out)
    tc_gemm<true, false, true><<<dim3(FF/128, MM/128), 256, GEMM_SMEM>>>(z, wt1, b1, nullptr, u, FF, DD);

    // 9) FFN2 + bias + residual(y) -> out (fp32)
    tc_gemm<false, true, false><<<dim3(DD/128, MM/128), 256, GEMM_SMEM>>>(u, wt2, b2, y, out, DD, FF);
}

// round 15
// speedup vs baseline: 1.7360x; 1.1580x over previous
#include <cuda_runtime.h>
#include <cuda_bf16.h>
#include <math.h>
#include <cstdint>

// ---------------- problem dims (fixed) ----------------
#define BB   2
#define SS   2048
#define DD   768
#define HH   12
#define DK   64
#define FF   3072
#define MM   (BB*SS)          // 4096 tokens
#define NQKV (3*DD)           // 2304 fused QKV cols

// ---------------- scratch (device globals; allocation-free) ----------------
__device__ float g_h[MM*DD];            // LN1 output (tf32-rounded)
__device__ float g_qkv[MM*NQKV];        // fused QKV [M, 2304] (tf32-rounded)
__device__ __nv_bfloat16 g_vt16[BB*HH*DK*SS]; // V transposed [bh][d][s], bf16
__device__ float g_o[MM*DD];            // attn output (tf32-rounded)
__device__ float g_y[MM*DD];            // after O-proj + residual (fp32)
__device__ float g_z[MM*DD];            // LN2 output (tf32-rounded)
__device__ float g_u[MM*FF];            // FFN hidden (tf32-rounded)
__device__ float g_wtq[NQKV*DD];        // fused QKV weights^T (tf32)
__device__ float g_btq[NQKV];           // fused QKV bias
__device__ float g_wto[DD*DD];          // wo^T (tf32)
__device__ float g_wt1[FF*DD];          // w1^T (tf32)
__device__ float g_wt2[DD*FF];          // w2^T (tf32)

// ================= helpers =================
__device__ __forceinline__ uint32_t f2tf(float f) {
    uint32_t u; asm("cvt.rna.tf32.f32 %0, %1;" : "=r"(u) : "f"(f)); return u;
}
__device__ __forceinline__ float f2tff(float f) { return __uint_as_float(f2tf(f)); }
__device__ __forceinline__ uint32_t smem_u32(const void* p) {
    uint32_t a;
    asm("{ .reg .u64 t; cvta.to.shared.u64 t, %1; cvt.u32.u64 %0, t; }" : "=r"(a) : "l"(p));
    return a;
}
__device__ __forceinline__ void mma8(float* c, const uint32_t* a, const uint32_t* b) {
    asm volatile("mma.sync.aligned.m16n8k8.row.col.f32.tf32.tf32.f32 "
        "{%0,%1,%2,%3}, {%4,%5,%6,%7}, {%8,%9}, {%0,%1,%2,%3};"
        : "+f"(c[0]), "+f"(c[1]), "+f"(c[2]), "+f"(c[3])
        : "r"(a[0]), "r"(a[1]), "r"(a[2]), "r"(a[3]), "r"(b[0]), "r"(b[1]));
}
__device__ __forceinline__ void mma16bf(float* c, const uint32_t* a, const uint32_t* b) {
    asm volatile("mma.sync.aligned.m16n8k16.row.col.f32.bf16.bf16.f32 "
        "{%0,%1,%2,%3}, {%4,%5,%6,%7}, {%8,%9}, {%0,%1,%2,%3};"
        : "+f"(c[0]), "+f"(c[1]), "+f"(c[2]), "+f"(c[3])
        : "r"(a[0]), "r"(a[1]), "r"(a[2]), "r"(a[3]), "r"(b[0]), "r"(b[1]));
}
__device__ __forceinline__ uint32_t packbf(float lo, float hi) {
    uint32_t d;
    asm("cvt.rn.bf16x2.f32 %0, %1, %2;" : "=r"(d) : "f"(hi), "f"(lo));
    return d;
}
__device__ __forceinline__ float gelu_f(float v) {
    return 0.5f * v * (1.0f + erff(v * 0.70710678118654752f));
}
__device__ __forceinline__ void cp16(uint32_t dst, const void* src) {
    asm volatile("cp.async.cg.shared.global [%0], [%1], 16;" :: "r"(dst), "l"(src));
}
#define CP_COMMIT() asm volatile("cp.async.commit_group;" ::: "memory")
#define CP_WAIT0()  asm volatile("cp.async.wait_group 0;" ::: "memory")
#define CP_WAIT1()  asm volatile("cp.async.wait_group 1;" ::: "memory")

// ---------------- LayerNorm: one block per row, tf32-rounded output -------
__global__ void __launch_bounds__(256) ln_kernel(
    const float* __restrict__ x, const float* __restrict__ gw,
    const float* __restrict__ bw, float* __restrict__ out)
{
    __shared__ float red[8];
    int row = blockIdx.x;
    int tid = threadIdx.x;
    const float* xr = x + (size_t)row * DD;

    float v0 = xr[tid], v1 = xr[tid + 256], v2 = xr[tid + 512];
    float s = v0 + v1 + v2;
    #pragma unroll
    for (int o = 16; o > 0; o >>= 1) s += __shfl_xor_sync(0xffffffffu, s, o);
    if ((tid & 31) == 0) red[tid >> 5] = s;
    __syncthreads();
    float tot = red[0]+red[1]+red[2]+red[3]+red[4]+red[5]+red[6]+red[7];
    float mu = tot * (1.0f / 768.0f);
    float d0 = v0 - mu, d1 = v1 - mu, d2 = v2 - mu;
    float q = d0*d0 + d1*d1 + d2*d2;
    #pragma unroll
    for (int o = 16; o > 0; o >>= 1) q += __shfl_xor_sync(0xffffffffu, q, o);
    __syncthreads();
    if ((tid & 31) == 0) red[tid >> 5] = q;
    __syncthreads();
    float vtot = red[0]+red[1]+red[2]+red[3]+red[4]+red[5]+red[6]+red[7];
    float rstd = rsqrtf(vtot * (1.0f / 768.0f) + 1e-5f);
    float* orow = out + (size_t)row * DD;
    orow[tid]       = f2tff(d0 * rstd * gw[tid]       + bw[tid]);
    orow[tid + 256] = f2tff(d1 * rstd * gw[tid + 256] + bw[tid + 256]);
    orow[tid + 512] = f2tff(d2 * rstd * gw[tid + 512] + bw[tid + 512]);
}

// ---------------- weight prep: transposes + packs (tf32) ------------------
__device__ __forceinline__ void trans_tile(
    const float* __restrict__ W, float* __restrict__ Wt, int K, int N,
    int bx, int by, float t[32][33], int tx, int ty)
{
    #pragma unroll
    for (int l = 0; l < 4; l++) {
        int k = by * 32 + ty + l * 8;
        t[ty + l * 8][tx] = W[(size_t)k * N + bx * 32 + tx];
    }
    __syncthreads();
    #pragma unroll
    for (int l = 0; l < 4; l++) {
        int n = bx * 32 + ty + l * 8;
        Wt[(size_t)n * K + by * 32 + tx] = f2tff(t[tx][ty + l * 8]);
    }
}

// grid: 1728 (qkv) + 576 (wo) + 2304 (w1) + 2304 (w2) = 6912
__global__ void __launch_bounds__(256) prep_w_kernel(
    const float* __restrict__ wq, const float* __restrict__ wk,
    const float* __restrict__ wv, const float* __restrict__ wo,
    const float* __restrict__ w1, const float* __restrict__ w2,
    float* __restrict__ wtq, float* __restrict__ wto,
    float* __restrict__ wt1, float* __restrict__ wt2)
{
    __shared__ float t[32][33];
    int id = blockIdx.x;
    int tx = threadIdx.x, ty = threadIdx.y;
    if (id < 1728) {
        int p = id / 576, rem = id % 576;
        int bx = rem % 24, by = rem / 24;
        const float* wp = (p == 0) ? wq : (p == 1) ? wk : wv;
        int np0 = bx * 32, d0 = by * 32;
        int hh = np0 >> 6, kk0 = np0 & 63;
        #pragma unroll
        for (int l = 0; l < 4; l++) {
            int d = d0 + ty + l * 8;
            t[ty + l * 8][tx] = wp[((size_t)hh * DD + d) * DK + kk0 + tx];
        }
        __syncthreads();
        #pragma unroll
        for (int l = 0; l < 4; l++) {
            int n = np0 + ty + l * 8;
            wtq[((size_t)p * DD + n) * DD + d0 + tx] = f2tff(t[tx][ty + l * 8]);
        }
    } else if (id < 2304) {
        int rem = id - 1728;
        trans_tile(wo, wto, DD, DD, rem % 24, rem / 24, t, tx, ty);
    } else if (id < 4608) {
        int rem = id - 2304;
        trans_tile(w1, wt1, DD, FF, rem % 96, rem / 96, t, tx, ty);
    } else {
        int rem = id - 4608;
        trans_tile(w2, wt2, FF, DD, rem % 24, rem / 24, t, tx, ty);
    }
}

__global__ void qkv_bias_kernel(
    const float* __restrict__ bq, const float* __restrict__ bk,
    const float* __restrict__ bv, float* __restrict__ bt)
{
    int i = blockIdx.x * 256 + threadIdx.x;   // grid 3, 256 thr
    if (i < DD) { bt[i] = bq[i]; bt[DD + i] = bk[i]; bt[2 * DD + i] = bv[i]; }
}

// ---------------- V transpose: qkv V-part -> vt16[bh][d][s] bf16 ----------
__global__ void __launch_bounds__(256) vtrans_kernel(
    const float* __restrict__ qkv, __nv_bfloat16* __restrict__ vt16)
{
    __shared__ float t[32][33];
    int s0 = blockIdx.x * 32;
    int d0 = blockIdx.y * 32;
    int bh = blockIdx.z;
    int b_ = bh / HH, h_ = bh % HH;
    int tx = threadIdx.x, ty = threadIdx.y;
    #pragma unroll
    for (int l = 0; l < 4; l++) {
        int s = s0 + ty + l * 8;
        t[ty + l * 8][tx] = qkv[((size_t)(b_ * SS + s)) * NQKV + 2 * DD + h_ * 64 + d0 + tx];
    }
    __syncthreads();
    if (tx < 16) {
        #pragma unroll
        for (int l = 0; l < 4; l++) {
            int d = d0 + ty + l * 8;
            uint32_t w = packbf(t[2 * tx][ty + l * 8], t[2 * tx + 1][ty + l * 8]);
            uint32_t* orow = (uint32_t*)(vt16 + ((size_t)bh * 64 + d) * SS + s0);
            orow[tx] = w;
        }
    }
}

// ============ TF32 mma.sync GEMM v3: C[M,N] = A[M,K] @ Bt[N,K]^T ==========
// Block 128x128, BK=32, 128 threads = 4 warps (2m x 2n), warp tile 64x64.
// Staging: cp.async.cg 16B into raw row-major tiles with chunk^=(row&7)
// swizzle (no registers). Fragments read with conflict-free scalar LDS.32.
// smem 64KB: sA[2][4096] words, sB[2][4096] words.
#define GEMM_SMEM (16384 * 4)

template<bool GELU, bool RES, bool TFOUT>
__global__ void __launch_bounds__(128, 2) tc_gemm(
    const float* __restrict__ A, const float* __restrict__ Bt,
    const float* __restrict__ bias, const float* __restrict__ res,
    float* __restrict__ C, int N, int K)
{
    extern __shared__ uint32_t sh[];
    uint32_t shb = smem_u32(sh);
    int tid = threadIdx.x, lane = tid & 31, wid = tid >> 5;
    int wm = wid & 1, wn = wid >> 1;
    int bm = blockIdx.y, bn = blockIdx.x;
    int g = lane >> 2, T = lane & 3;

    const float* Ag = A  + (size_t)(bm * 128) * K;
    const float* Bg = Bt + (size_t)(bn * 128) * K;

    // cp.async geometry: thread -> rows r0+16i, chunk c (16B), swizzled dst
    int r0 = tid >> 3, c = tid & 7;
    uint32_t dstA = (uint32_t)(r0 * 32 + ((c ^ (r0 & 7)) << 2));  // word offset
    const float* srcA = Ag + (size_t)r0 * K + c * 4;
    const float* srcB = Bg + (size_t)r0 * K + c * 4;

    float acc[4][8][4];
    #pragma unroll
    for (int mi = 0; mi < 4; mi++)
        #pragma unroll
        for (int ni = 0; ni < 8; ni++)
            #pragma unroll
            for (int r = 0; r < 4; r++) acc[mi][ni][r] = 0.0f;

    // prologue: stage chunk 0 into buffer 0
    #pragma unroll
    for (int i = 0; i < 8; i++) {
        cp16(shb + (dstA + i * 512) * 4,        srcA + (size_t)i * 16 * K);
        cp16(shb + (8192 + dstA + i * 512) * 4, srcB + (size_t)i * 16 * K);
    }
    CP_COMMIT();

    int NT = K >> 5;
    for (int t = 0; t < NT; t++) {
        if (t + 1 < NT) {
            int k0 = (t + 1) * 32;
            uint32_t base = ((t + 1) & 1) * 4096;
            #pragma unroll
            for (int i = 0; i < 8; i++) {
                cp16(shb + (base + dstA + i * 512) * 4,
                     srcA + (size_t)i * 16 * K + k0);
                cp16(shb + (8192 + base + dstA + i * 512) * 4,
                     srcB + (size_t)i * 16 * K + k0);
            }
            CP_COMMIT();
            CP_WAIT1();
        } else {
            CP_WAIT0();
        }
        __syncthreads();

        const uint32_t* cA = sh + (t & 1) * 4096;
        const uint32_t* cB = sh + 8192 + (t & 1) * 4096;
        int aBase = (wm * 64 + g) * 32 + T;
        int bBase = (wn * 64 + g) * 32 + T;

        #pragma unroll
        for (int ks = 0; ks < 4; ks++) {
            int s0 = (((ks * 2)     ^ g) << 2);
            int s1 = (((ks * 2 + 1) ^ g) << 2);
            uint32_t ua[4][4];
            #pragma unroll
            for (int mi = 0; mi < 4; mi++) {
                int ab = aBase + mi * 512;
                ua[mi][0] = cA[ab + s0];
                ua[mi][1] = cA[ab + 256 + s0];
                ua[mi][2] = cA[ab + s1];
                ua[mi][3] = cA[ab + 256 + s1];
            }
            uint32_t ub[8][2];
            #pragma unroll
            for (int ni = 0; ni < 8; ni++) {
                int bb = bBase + ni * 256;
                ub[ni][0] = cB[bb + s0];
                ub[ni][1] = cB[bb + s1];
            }
            #pragma unroll
            for (int mi = 0; mi < 4; mi++)
                #pragma unroll
                for (int ni = 0; ni < 8; ni++)
                    mma8(acc[mi][ni], ua[mi], ub[ni]);
        }
        __syncthreads();
    }

    // epilogue
    #pragma unroll
    for (int mi = 0; mi < 4; mi++) {
        int row0e = bm * 128 + wm * 64 + mi * 16 + g;
        #pragma unroll
        for (int ni = 0; ni < 8; ni++) {
            int col = bn * 128 + wn * 64 + ni * 8 + 2 * T;
            float b0 = bias[col], b1 = bias[col + 1];
            #pragma unroll
            for (int hh = 0; hh < 2; hh++) {
                int rr = row0e + hh * 8;
                float v0 = acc[mi][ni][2*hh]   + b0;
                float v1 = acc[mi][ni][2*hh+1] + b1;
                if (GELU) { v0 = gelu_f(v0); v1 = gelu_f(v1); }
                if (RES) {
                    float2 rv = *(const float2*)(res + (size_t)rr * N + col);
                    v0 += rv.x; v1 += rv.y;
                }
                if (TFOUT) { v0 = f2tff(v0); v1 = f2tff(v1); }
                *(float2*)(C + (size_t)rr * N + col) = make_float2(v0, v1);
            }
        }
    }
}

// ============ flash attention (R14: 8 warps x 16q, S tf32 / PV bf16) ======
#define ATTN_SMEM ((8192 + 4096 + 2048) * 4)

__global__ void __launch_bounds__(256, 2) attn_kernel(
    const float* __restrict__ qkv, const __nv_bfloat16* __restrict__ vt16,
    float* __restrict__ o)
{
    extern __shared__ uint32_t sh[];
    uint32_t* QF = sh;            // [warp8][ks8][lane32][4]
    uint32_t* KF = sh + 8192;     // [na8][ks8][lane32][2]
    uint32_t* VF = sh + 12288;    // [na8][kt4][lane32][2] bf16x2

    int tid = threadIdx.x, lane = tid & 31, wid = tid >> 5;
    int g = lane >> 2, T = lane & 3;
    int bh = blockIdx.y, b_ = bh / HH, h_ = bh % HH;
    int q0 = blockIdx.x * 128;
    size_t baseTok = (size_t)b_ * SS;

    int cg = tid & 15, ksq = cg >> 1, hfq = cg & 1;
    int sw = ksq & 3;
    int p0 = ((0 ^ sw) << 1), p1 = ((1 ^ sw) << 1),
        p2 = ((2 ^ sw) << 1), p3 = ((3 ^ sw) << 1);

    // ---- stage Q (pre-scaled by log2e/8: exp2-domain softmax) ----
    const float QSCALE = 0.125f * 1.44269504088896340736f;
    #pragma unroll
    for (int i = 0; i < 8; i++) {
        int r = (tid >> 4) + i * 16;
        int wf = r >> 4, row = r & 15;
        int d = ((wf * 8 + ksq) * 32 + (row & 7) * 4) * 4 + (row >> 3) + 2 * hfq;
        float4 v = *(const float4*)(qkv + (baseTok + q0 + r) * NQKV + h_ * 64 + cg * 4);
        QF[d + (p0<<1)] = __float_as_uint(v.x * QSCALE);
        QF[d + (p1<<1)] = __float_as_uint(v.y * QSCALE);
        QF[d + (p2<<1)] = __float_as_uint(v.z * QSCALE);
        QF[d + (p3<<1)] = __float_as_uint(v.w * QSCALE);
    }

    int kD[4]; size_t kS[4];
    #pragma unroll
    for (int i = 0; i < 4; i++) {
        int key = (tid >> 4) + i * 16;
        kD[i] = (((key >> 3) * 8 + ksq) * 32 + (key & 7) * 4) * 2 + hfq;
        kS[i] = (baseTok + key) * NQKV + DD + h_ * 64 + cg * 4;
    }
    int vd = tid >> 2, vkt = tid & 3;
    int vslot = (((vd >> 3) * 4 + vkt) * 32 + (vd & 7) * 4) * 2;
    const __nv_bfloat16* vrow = vt16 + ((size_t)bh * 64 + vd) * SS + vkt * 16;

    float oacc[8][4];
    #pragma unroll
    for (int na = 0; na < 8; na++)
        #pragma unroll
        for (int r = 0; r < 4; r++) oacc[na][r] = 0.0f;
    float m0 = -1e30f, m1 = -1e30f, l0 = 0.0f, l1 = 0.0f;

    float4 kreg[4]; uint4 vreg[2];
    #pragma unroll
    for (int i = 0; i < 4; i++) kreg[i] = *(const float4*)(qkv + kS[i]);
    vreg[0] = *(const uint4*)(vrow);
    vreg[1] = *(const uint4*)(vrow + 8);

    for (int s0 = 0; s0 < SS; s0 += 64) {
        __syncthreads();
        #pragma unroll
        for (int i = 0; i < 4; i++) {
            KF[kD[i]+p0] = __float_as_uint(kreg[i].x);
            KF[kD[i]+p1] = __float_as_uint(kreg[i].y);
            KF[kD[i]+p2] = __float_as_uint(kreg[i].z);
            KF[kD[i]+p3] = __float_as_uint(kreg[i].w);
        }
        {
            const uint32_t* w1 = (const uint32_t*)&vreg[0];
            const uint32_t* w2 = (const uint32_t*)&vreg[1];
            #pragma unroll
            for (int Ti = 0; Ti < 4; Ti++)
                *(uint2*)&VF[vslot + Ti * 2] = make_uint2(w1[Ti], w2[Ti]);
        }
        __syncthreads();
        if (s0 + 64 < SS) {
            #pragma unroll
            for (int i = 0; i < 4; i++)
                kreg[i] = *(const float4*)(qkv + kS[i] + (size_t)(s0 + 64) * NQKV);
            vreg[0] = *(const uint4*)(vrow + s0 + 64);
            vreg[1] = *(const uint4*)(vrow + s0 + 72);
        }

        // S = Q @ K^T (tf32)
        float sacc[8][4];
        #pragma unroll
        for (int na = 0; na < 8; na++)
            #pragma unroll
            for (int r = 0; r < 4; r++) sacc[na][r] = 0.0f;
        #pragma unroll
        for (int ks = 0; ks < 8; ks++) {
            int lx = lane ^ (ks & 3);
            uint32_t qa[4];
            *(uint4*)qa = *(const uint4*)&QF[((wid * 8 + ks) * 32 + lx) * 4];
            #pragma unroll
            for (int na = 0; na < 8; na++) {
                uint32_t kb[2];
                *(uint2*)kb = *(const uint2*)&KF[((na * 8 + ks) * 32 + lx) * 2];
                mma8(sacc[na], qa, kb);
            }
        }

        // online softmax (exp2 domain); pack P into bf16 A-fragments
        float rm0 = -1e30f, rm1 = -1e30f;
        #pragma unroll
        for (int na = 0; na < 8; na++) {
            rm0 = fmaxf(rm0, fmaxf(sacc[na][0], sacc[na][1]));
            rm1 = fmaxf(rm1, fmaxf(sacc[na][2], sacc[na][3]));
        }
        rm0 = fmaxf(rm0, __shfl_xor_sync(0xffffffffu, rm0, 1));
        rm0 = fmaxf(rm0, __shfl_xor_sync(0xffffffffu, rm0, 2));
        rm1 = fmaxf(rm1, __shfl_xor_sync(0xffffffffu, rm1, 1));
        rm1 = fmaxf(rm1, __shfl_xor_sync(0xffffffffu, rm1, 2));
        float mn0 = fmaxf(m0, rm0), mn1 = fmaxf(m1, rm1);
        float al0 = exp2f(m0 - mn0), al1 = exp2f(m1 - mn1);
        m0 = mn0; m1 = mn1;
        float rs0 = 0.0f, rs1 = 0.0f;
        uint32_t pregs[4][4];
        #pragma unroll
        for (int na = 0; na < 8; na++) {
            float e0 = exp2f(sacc[na][0] - mn0);
            float e1 = exp2f(sacc[na][1] - mn0);
            float e2 = exp2f(sacc[na][2] - mn1);
            float e3 = exp2f(sacc[na][3] - mn1);
            rs0 += e0 + e1; rs1 += e2 + e3;
            int kt = na >> 1;
            if ((na & 1) == 0) {
                pregs[kt][0] = packbf(e0, e1);
                pregs[kt][1] = packbf(e2, e3);
            } else {
                pregs[kt][2] = packbf(e0, e1);
                pregs[kt][3] = packbf(e2, e3);
            }
        }
        rs0 += __shfl_xor_sync(0xffffffffu, rs0, 1);
        rs0 += __shfl_xor_sync(0xffffffffu, rs0, 2);
        rs1 += __shfl_xor_sync(0xffffffffu, rs1, 1);
        rs1 += __shfl_xor_sync(0xffffffffu, rs1, 2);
        l0 = l0 * al0 + rs0; l1 = l1 * al1 + rs1;
        #pragma unroll
        for (int na = 0; na < 8; na++) {
            oacc[na][0] *= al0; oacc[na][1] *= al0;
            oacc[na][2] *= al1; oacc[na][3] *= al1;
        }

        // O += P @ V (bf16 m16n8k16)
        #pragma unroll
        for (int kt = 0; kt < 4; kt++) {
            #pragma unroll
            for (int na = 0; na < 8; na++) {
                uint32_t vb[2];
                *(uint2*)vb = *(const uint2*)&VF[((na * 4 + kt) * 32 + lane) * 2];
                mma16bf(oacc[na], pregs[kt], vb);
            }
        }
    }

    float inv0 = 1.0f / l0, inv1 = 1.0f / l1;
    int row0 = q0 + wid * 16 + g;
    #pragma unroll
    for (int na = 0; na < 8; na++) {
        int col = h_ * 64 + na * 8 + 2 * T;
        *(float2*)(o + (baseTok + row0)     * DD + col) =
            make_float2(f2tff(oacc[na][0] * inv0), f2tff(oacc[na][1] * inv0));
        *(float2*)(o + (baseTok + row0 + 8) * DD + col) =
            make_float2(f2tff(oacc[na][2] * inv1), f2tff(oacc[na][3] * inv1));
    }
}

// ---------------- launch ---------------------------------------------------
extern "C" void kernel_launch(void* const* d_in, const int* in_sizes, int n_in,
                              void* d_out, int out_size)
{
    (void)in_sizes; (void)n_in; (void)out_size;
    const float* x    = (const float*)d_in[0];
    const float* wq_w = (const float*)d_in[1];
    const float* wq_b = (const float*)d_in[2];
    const float* wk_w = (const float*)d_in[3];
    const float* wk_b = (const float*)d_in[4];
    const float* wv_w = (const float*)d_in[5];
    const float* wv_b = (const float*)d_in[6];
    const float* wo_w = (const float*)d_in[7];
    const float* wo_b = (const float*)d_in[8];
    const float* ln_g = (const float*)d_in[9];
    const float* ln_b = (const float*)d_in[10];
    const float* w1   = (const float*)d_in[11];
    const float* b1   = (const float*)d_in[12];
    const float* w2   = (const float*)d_in[13];
    const float* b2   = (const float*)d_in[14];
    float* out = (float*)d_out;

    float *h, *qkv, *o, *y, *z, *u, *wtq, *btq, *wto, *wt1, *wt2;
    __nv_bfloat16* vt16;
    cudaGetSymbolAddress((void**)&h,    g_h);
    cudaGetSymbolAddress((void**)&qkv,  g_qkv);
    cudaGetSymbolAddress((void**)&vt16, g_vt16);
    cudaGetSymbolAddress((void**)&o,    g_o);
    cudaGetSymbolAddress((void**)&y,    g_y);
    cudaGetSymbolAddress((void**)&z,    g_z);
    cudaGetSymbolAddress((void**)&u,    g_u);
    cudaGetSymbolAddress((void**)&wtq,  g_wtq);
    cudaGetSymbolAddress((void**)&btq,  g_btq);
    cudaGetSymbolAddress((void**)&wto,  g_wto);
    cudaGetSymbolAddress((void**)&wt1,  g_wt1);
    cudaGetSymbolAddress((void**)&wt2,  g_wt2);

    cudaFuncSetAttribute(tc_gemm<false, false, true >, cudaFuncAttributeMaxDynamicSharedMemorySize, GEMM_SMEM);
    cudaFuncSetAttribute(tc_gemm<false, true,  false>, cudaFuncAttributeMaxDynamicSharedMemorySize, GEMM_SMEM);
    cudaFuncSetAttribute(tc_gemm<true,  false, true >, cudaFuncAttributeMaxDynamicSharedMemorySize, GEMM_SMEM);
    cudaFuncSetAttribute(attn_kernel, cudaFuncAttributeMaxDynamicSharedMemorySize, ATTN_SMEM);

    // 0) weight prep
    prep_w_kernel<<<6912, dim3(32, 8)>>>(wq_w, wk_w, wv_w, wo_w, w1, w2,
                                         wtq, wto, wt1, wt2);
    // 1) qkv bias pack
    qkv_bias_kernel<<<3, 256>>>(wq_b, wk_b, wv_b, btq);

    // 2) LN1 (tf32 out)
    ln_kernel<<<MM, 256>>>(x, ln_g, ln_b, h);

    // 3) fused QKV projection (tf32 out)  [capture slot 3 -> ncu]
    tc_gemm<false, false, true><<<dim3(NQKV/128, MM/128), 128, GEMM_SMEM>>>(h, wtq, btq, nullptr, qkv, NQKV, DD);

    // 4) V transpose+bf16 pack
    vtrans_kernel<<<dim3(SS/32, 2, BB*HH), dim3(32, 8)>>>(qkv, vt16);

    // 5) attention
    attn_kernel<<<dim3(SS/128, BB*HH), 256, ATTN_SMEM>>>(qkv, vt16, o);

    // 6) O-proj + bias + residual(x) -> fp32 y
    tc_gemm<false, true, false><<<dim3(DD/128, MM/128), 128, GEMM_SMEM>>>(o, wto, wo_b, x, y, DD, DD);

    // 7) LN2 (tf32 out)
    ln_kernel<<<MM, 256>>>(y, ln_g, ln_b, z);

    // 8) FFN1 + bias + exact GELU (tf32 out)
    tc_gemm<true, false, true><<<dim3(FF/128, MM/128), 128, GEMM_SMEM>>>(z, wt1, b1, nullptr, u, FF, DD);

    // 9) FFN2 + bias + residual(y) -> out (fp32)
    tc_gemm<false, true, false><<<dim3(DD/128, MM/128), 128, GEMM_SMEM>>>(u, wt2, b2, y, out, DD, FF);
}

// round 17
// speedup vs baseline: 1.8656x; 1.0747x over previous
#include <cuda_runtime.h>
#include <cuda_bf16.h>
#include <math.h>
#include <cstdint>

// ---------------- problem dims (fixed) ----------------
#define BB   2
#define SS   2048
#define DD   768
#define HH   12
#define DK   64
#define FF   3072
#define MM   (BB*SS)          // 4096 tokens
#define NQKV (3*DD)           // 2304 fused QKV cols

// ---------------- scratch (device globals; allocation-free) ----------------
__device__ float g_h[MM*DD];            // LN1 output (tf32-rounded)
__device__ float g_qkv[MM*NQKV];        // fused QKV [M, 2304] (tf32-rounded)
__device__ __nv_bfloat16 g_vt16[BB*HH*DK*SS]; // V transposed [bh][d][s], bf16
__device__ float g_o[MM*DD];            // attn output (tf32-rounded)
__device__ float g_y[MM*DD];            // after O-proj + residual (fp32)
__device__ float g_z[MM*DD];            // LN2 output (tf32-rounded)
__device__ float g_u[MM*FF];            // FFN hidden (tf32-rounded)
__device__ float g_wtq[NQKV*DD];        // fused QKV weights^T (tf32)
__device__ float g_btq[NQKV];           // fused QKV bias
__device__ float g_wto[DD*DD];          // wo^T (tf32)
__device__ float g_wt1[FF*DD];          // w1^T (tf32)
__device__ float g_wt2[DD*FF];          // w2^T (tf32)

// ================= helpers =================
__device__ __forceinline__ uint32_t f2tf(float f) {
    uint32_t u; asm("cvt.rna.tf32.f32 %0, %1;" : "=r"(u) : "f"(f)); return u;
}
__device__ __forceinline__ float f2tff(float f) { return __uint_as_float(f2tf(f)); }
__device__ __forceinline__ uint32_t smem_u32(const void* p) {
    uint32_t a;
    asm("{ .reg .u64 t; cvta.to.shared.u64 t, %1; cvt.u32.u64 %0, t; }" : "=r"(a) : "l"(p));
    return a;
}
__device__ __forceinline__ void mma8(float* c, const uint32_t* a, const uint32_t* b) {
    asm volatile("mma.sync.aligned.m16n8k8.row.col.f32.tf32.tf32.f32 "
        "{%0,%1,%2,%3}, {%4,%5,%6,%7}, {%8,%9}, {%0,%1,%2,%3};"
        : "+f"(c[0]), "+f"(c[1]), "+f"(c[2]), "+f"(c[3])
        : "r"(a[0]), "r"(a[1]), "r"(a[2]), "r"(a[3]), "r"(b[0]), "r"(b[1]));
}
__device__ __forceinline__ void mma16bf(float* c, const uint32_t* a, const uint32_t* b) {
    asm volatile("mma.sync.aligned.m16n8k16.row.col.f32.bf16.bf16.f32 "
        "{%0,%1,%2,%3}, {%4,%5,%6,%7}, {%8,%9}, {%0,%1,%2,%3};"
        : "+f"(c[0]), "+f"(c[1]), "+f"(c[2]), "+f"(c[3])
        : "r"(a[0]), "r"(a[1]), "r"(a[2]), "r"(a[3]), "r"(b[0]), "r"(b[1]));
}
__device__ __forceinline__ uint32_t packbf(float lo, float hi) {
    uint32_t d;
    asm("cvt.rn.bf16x2.f32 %0, %1, %2;" : "=r"(d) : "f"(hi), "f"(lo));
    return d;
}
__device__ __forceinline__ float gelu_f(float v) {
    return 0.5f * v * (1.0f + erff(v * 0.70710678118654752f));
}
__device__ __forceinline__ void cp16(uint32_t dst, const void* src) {
    asm volatile("cp.async.cg.shared.global [%0], [%1], 16;" :: "r"(dst), "l"(src));
}
#define CP_COMMIT() asm volatile("cp.async.commit_group;" ::: "memory")
#define CP_WAIT0()  asm volatile("cp.async.wait_group 0;" ::: "memory")
#define CP_WAIT1()  asm volatile("cp.async.wait_group 1;" ::: "memory")

// ---------------- LayerNorm: one block per row, tf32-rounded output -------
__global__ void __launch_bounds__(256) ln_kernel(
    const float* __restrict__ x, const float* __restrict__ gw,
    const float* __restrict__ bw, float* __restrict__ out)
{
    __shared__ float red[8];
    int row = blockIdx.x;
    int tid = threadIdx.x;
    const float* xr = x + (size_t)row * DD;

    float v0 = xr[tid], v1 = xr[tid + 256], v2 = xr[tid + 512];
    float s = v0 + v1 + v2;
    #pragma unroll
    for (int o = 16; o > 0; o >>= 1) s += __shfl_xor_sync(0xffffffffu, s, o);
    if ((tid & 31) == 0) red[tid >> 5] = s;
    __syncthreads();
    float tot = red[0]+red[1]+red[2]+red[3]+red[4]+red[5]+red[6]+red[7];
    float mu = tot * (1.0f / 768.0f);
    float d0 = v0 - mu, d1 = v1 - mu, d2 = v2 - mu;
    float q = d0*d0 + d1*d1 + d2*d2;
    #pragma unroll
    for (int o = 16; o > 0; o >>= 1) q += __shfl_xor_sync(0xffffffffu, q, o);
    __syncthreads();
    if ((tid & 31) == 0) red[tid >> 5] = q;
    __syncthreads();
    float vtot = red[0]+red[1]+red[2]+red[3]+red[4]+red[5]+red[6]+red[7];
    float rstd = rsqrtf(vtot * (1.0f / 768.0f) + 1e-5f);
    float* orow = out + (size_t)row * DD;
    orow[tid]       = f2tff(d0 * rstd * gw[tid]       + bw[tid]);
    orow[tid + 256] = f2tff(d1 * rstd * gw[tid + 256] + bw[tid + 256]);
    orow[tid + 512] = f2tff(d2 * rstd * gw[tid + 512] + bw[tid + 512]);
}

// ---------------- weight prep: transposes + packs (tf32) ------------------
__device__ __forceinline__ void trans_tile(
    const float* __restrict__ W, float* __restrict__ Wt, int K, int N,
    int bx, int by, float t[32][33], int tx, int ty)
{
    #pragma unroll
    for (int l = 0; l < 4; l++) {
        int k = by * 32 + ty + l * 8;
        t[ty + l * 8][tx] = W[(size_t)k * N + bx * 32 + tx];
    }
    __syncthreads();
    #pragma unroll
    for (int l = 0; l < 4; l++) {
        int n = bx * 32 + ty + l * 8;
        Wt[(size_t)n * K + by * 32 + tx] = f2tff(t[tx][ty + l * 8]);
    }
}

// grid: 1728 (qkv) + 576 (wo) + 2304 (w1) + 2304 (w2) = 6912
__global__ void __launch_bounds__(256) prep_w_kernel(
    const float* __restrict__ wq, const float* __restrict__ wk,
    const float* __restrict__ wv, const float* __restrict__ wo,
    const float* __restrict__ w1, const float* __restrict__ w2,
    float* __restrict__ wtq, float* __restrict__ wto,
    float* __restrict__ wt1, float* __restrict__ wt2)
{
    __shared__ float t[32][33];
    int id = blockIdx.x;
    int tx = threadIdx.x, ty = threadIdx.y;
    if (id < 1728) {
        int p = id / 576, rem = id % 576;
        int bx = rem % 24, by = rem / 24;
        const float* wp = (p == 0) ? wq : (p == 1) ? wk : wv;
        int np0 = bx * 32, d0 = by * 32;
        int hh = np0 >> 6, kk0 = np0 & 63;
        #pragma unroll
        for (int l = 0; l < 4; l++) {
            int d = d0 + ty + l * 8;
            t[ty + l * 8][tx] = wp[((size_t)hh * DD + d) * DK + kk0 + tx];
        }
        __syncthreads();
        #pragma unroll
        for (int l = 0; l < 4; l++) {
            int n = np0 + ty + l * 8;
            wtq[((size_t)p * DD + n) * DD + d0 + tx] = f2tff(t[tx][ty + l * 8]);
        }
    } else if (id < 2304) {
        int rem = id - 1728;
        trans_tile(wo, wto, DD, DD, rem % 24, rem / 24, t, tx, ty);
    } else if (id < 4608) {
        int rem = id - 2304;
        trans_tile(w1, wt1, DD, FF, rem % 96, rem / 96, t, tx, ty);
    } else {
        int rem = id - 4608;
        trans_tile(w2, wt2, FF, DD, rem % 24, rem / 24, t, tx, ty);
    }
}

__global__ void qkv_bias_kernel(
    const float* __restrict__ bq, const float* __restrict__ bk,
    const float* __restrict__ bv, float* __restrict__ bt)
{
    int i = blockIdx.x * 256 + threadIdx.x;   // grid 3, 256 thr
    if (i < DD) { bt[i] = bq[i]; bt[DD + i] = bk[i]; bt[2 * DD + i] = bv[i]; }
}

// ---------------- V transpose: qkv V-part -> vt16[bh][d][s] bf16 ----------
__global__ void __launch_bounds__(256) vtrans_kernel(
    const float* __restrict__ qkv, __nv_bfloat16* __restrict__ vt16)
{
    __shared__ float t[32][33];
    int s0 = blockIdx.x * 32;
    int d0 = blockIdx.y * 32;
    int bh = blockIdx.z;
    int b_ = bh / HH, h_ = bh % HH;
    int tx = threadIdx.x, ty = threadIdx.y;
    #pragma unroll
    for (int l = 0; l < 4; l++) {
        int s = s0 + ty + l * 8;
        t[ty + l * 8][tx] = qkv[((size_t)(b_ * SS + s)) * NQKV + 2 * DD + h_ * 64 + d0 + tx];
    }
    __syncthreads();
    if (tx < 16) {
        #pragma unroll
        for (int l = 0; l < 4; l++) {
            int d = d0 + ty + l * 8;
            uint32_t w = packbf(t[2 * tx][ty + l * 8], t[2 * tx + 1][ty + l * 8]);
            uint32_t* orow = (uint32_t*)(vt16 + ((size_t)bh * 64 + d) * SS + s0);
            orow[tx] = w;
        }
    }
}

// ============ TF32 mma.sync GEMM v3 (unchanged from R15 — known good) =====
#define GEMM_SMEM (16384 * 4)

template<bool GELU, bool RES, bool TFOUT>
__global__ void __launch_bounds__(128, 2) tc_gemm(
    const float* __restrict__ A, const float* __restrict__ Bt,
    const float* __restrict__ bias, const float* __restrict__ res,
    float* __restrict__ C, int N, int K)
{
    extern __shared__ uint32_t sh[];
    uint32_t shb = smem_u32(sh);
    int tid = threadIdx.x, lane = tid & 31, wid = tid >> 5;
    int wm = wid & 1, wn = wid >> 1;
    int bm = blockIdx.y, bn = blockIdx.x;
    int g = lane >> 2, T = lane & 3;

    const float* Ag = A  + (size_t)(bm * 128) * K;
    const float* Bg = Bt + (size_t)(bn * 128) * K;

    int r0 = tid >> 3, c = tid & 7;
    uint32_t dstA = (uint32_t)(r0 * 32 + ((c ^ (r0 & 7)) << 2));
    const float* srcA = Ag + (size_t)r0 * K + c * 4;
    const float* srcB = Bg + (size_t)r0 * K + c * 4;

    float acc[4][8][4];
    #pragma unroll
    for (int mi = 0; mi < 4; mi++)
        #pragma unroll
        for (int ni = 0; ni < 8; ni++)
            #pragma unroll
            for (int r = 0; r < 4; r++) acc[mi][ni][r] = 0.0f;

    #pragma unroll
    for (int i = 0; i < 8; i++) {
        cp16(shb + (dstA + i * 512) * 4,        srcA + (size_t)i * 16 * K);
        cp16(shb + (8192 + dstA + i * 512) * 4, srcB + (size_t)i * 16 * K);
    }
    CP_COMMIT();

    int NT = K >> 5;
    for (int t = 0; t < NT; t++) {
        if (t + 1 < NT) {
            int k0 = (t + 1) * 32;
            uint32_t base = ((t + 1) & 1) * 4096;
            #pragma unroll
            for (int i = 0; i < 8; i++) {
                cp16(shb + (base + dstA + i * 512) * 4,
                     srcA + (size_t)i * 16 * K + k0);
                cp16(shb + (8192 + base + dstA + i * 512) * 4,
                     srcB + (size_t)i * 16 * K + k0);
            }
            CP_COMMIT();
            CP_WAIT1();
        } else {
            CP_WAIT0();
        }
        __syncthreads();

        const uint32_t* cA = sh + (t & 1) * 4096;
        const uint32_t* cB = sh + 8192 + (t & 1) * 4096;
        int aBase = (wm * 64 + g) * 32 + T;
        int bBase = (wn * 64 + g) * 32 + T;

        #pragma unroll
        for (int ks = 0; ks < 4; ks++) {
            int s0 = (((ks * 2)     ^ g) << 2);
            int s1 = (((ks * 2 + 1) ^ g) << 2);
            uint32_t ua[4][4];
            #pragma unroll
            for (int mi = 0; mi < 4; mi++) {
                int ab = aBase + mi * 512;
                ua[mi][0] = cA[ab + s0];
                ua[mi][1] = cA[ab + 256 + s0];
                ua[mi][2] = cA[ab + s1];
                ua[mi][3] = cA[ab + 256 + s1];
            }
            uint32_t ub[8][2];
            #pragma unroll
            for (int ni = 0; ni < 8; ni++) {
                int bb = bBase + ni * 256;
                ub[ni][0] = cB[bb + s0];
                ub[ni][1] = cB[bb + s1];
            }
            #pragma unroll
            for (int mi = 0; mi < 4; mi++)
                #pragma unroll
                for (int ni = 0; ni < 8; ni++)
                    mma8(acc[mi][ni], ua[mi], ub[ni]);
        }
        __syncthreads();
    }

    #pragma unroll
    for (int mi = 0; mi < 4; mi++) {
        int row0e = bm * 128 + wm * 64 + mi * 16 + g;
        #pragma unroll
        for (int ni = 0; ni < 8; ni++) {
            int col = bn * 128 + wn * 64 + ni * 8 + 2 * T;
            float b0 = bias[col], b1 = bias[col + 1];
            #pragma unroll
            for (int hh = 0; hh < 2; hh++) {
                int rr = row0e + hh * 8;
                float v0 = acc[mi][ni][2*hh]   + b0;
                float v1 = acc[mi][ni][2*hh+1] + b1;
                if (GELU) { v0 = gelu_f(v0); v1 = gelu_f(v1); }
                if (RES) {
                    float2 rv = *(const float2*)(res + (size_t)rr * N + col);
                    v0 += rv.x; v1 += rv.y;
                }
                if (TFOUT) { v0 = f2tff(v0); v1 = f2tff(v1); }
                *(float2*)(C + (size_t)rr * N + col) = make_float2(v0, v1);
            }
        }
    }
}

// ============ flash attention: all-bf16 mma (S and PV), fp32 softmax ======
// grid (S/128, B*H), 256 threads = 8 warps x 16q. smem 32KB:
//   QF [wf8][kt4][lane32][4]  bf16 a-frags (Q pre-scaled)     16KB
//   KF [na8][kt4][lane32][2]  bf16 b-frags, T^kt store swizzle  8KB
//   VF same shape for V                                          8KB
#define ATTN_SMEM ((4096 + 2048 + 2048) * 4)

__global__ void __launch_bounds__(256, 2) attn_kernel(
    const float* __restrict__ qkv, const __nv_bfloat16* __restrict__ vt16,
    float* __restrict__ o)
{
    extern __shared__ uint32_t sh[];
    uint32_t* QF = sh;            // 4096 words
    uint32_t* KF = sh + 4096;     // 2048 words
    uint32_t* VF = sh + 6144;     // 2048 words

    int tid = threadIdx.x, lane = tid & 31, wid = tid >> 5;
    int g = lane >> 2, T = lane & 3;
    int bh = blockIdx.y, b_ = bh / HH, h_ = bh % HH;
    int q0 = blockIdx.x * 128;
    size_t baseTok = (size_t)b_ * SS;

    // ---- stage Q as bf16 a-frags (pre-scaled by log2e/8) ----
    const float QSCALE = 0.125f * 1.44269504088896340736f;
    {
        int cg = tid & 15;
        int ktq = cg >> 2, dHi = (cg >> 1) & 1, T0 = (cg & 1) * 2;
        #pragma unroll
        for (int i = 0; i < 8; i++) {
            int r = (tid >> 4) + i * 16;
            int wf = r >> 4, row = r & 15;
            int gq = row & 7, reg = (row >> 3) + 2 * dHi;
            float4 v = *(const float4*)(qkv + (baseTok + q0 + r) * NQKV + h_ * 64 + cg * 4);
            int base = (((wf * 4 + ktq) * 32) + gq * 4 + T0) * 4 + reg;
            QF[base]     = packbf(v.x * QSCALE, v.y * QSCALE);
            QF[base + 4] = packbf(v.z * QSCALE, v.w * QSCALE);
        }
    }

    // K/V staging geometry: thread -> (key|d = tid>>2, kt = tid&3)
    int kv = tid >> 2, ktc = tid & 3;
    int fBase = (((kv >> 3) * 4 + ktc) * 32 + (kv & 7) * 4) * 2;   // + (Ti^kt)*2
    size_t kS = (baseTok + kv) * NQKV + DD + h_ * 64 + ktc * 16;
    const __nv_bfloat16* vrow = vt16 + ((size_t)bh * 64 + kv) * SS + ktc * 16;

    float oacc[8][4];
    #pragma unroll
    for (int na = 0; na < 8; na++)
        #pragma unroll
        for (int r = 0; r < 4; r++) oacc[na][r] = 0.0f;
    float m0 = -1e30f, m1 = -1e30f, l0 = 0.0f, l1 = 0.0f;

    // prefetch first K/V tile
    float4 kreg[4]; uint4 vreg[2];
    #pragma unroll
    for (int j = 0; j < 4; j++) kreg[j] = *(const float4*)(qkv + kS + j * 4);
    vreg[0] = *(const uint4*)(vrow);
    vreg[1] = *(const uint4*)(vrow + 8);

    for (int s0 = 0; s0 < SS; s0 += 64) {
        __syncthreads();   // prev-iter KF/VF readers done
        {
            // K: pack fp32 -> bf16x2 b-frags, store-side T^kt swizzle
            uint32_t r00 = packbf(kreg[0].x, kreg[0].y), r01 = packbf(kreg[2].x, kreg[2].y);
            uint32_t r10 = packbf(kreg[0].z, kreg[0].w), r11 = packbf(kreg[2].z, kreg[2].w);
            uint32_t r20 = packbf(kreg[1].x, kreg[1].y), r21 = packbf(kreg[3].x, kreg[3].y);
            uint32_t r30 = packbf(kreg[1].z, kreg[1].w), r31 = packbf(kreg[3].z, kreg[3].w);
            *(uint2*)&KF[fBase + ((0 ^ ktc) << 1)] = make_uint2(r00, r01);
            *(uint2*)&KF[fBase + ((1 ^ ktc) << 1)] = make_uint2(r10, r11);
            *(uint2*)&KF[fBase + ((2 ^ ktc) << 1)] = make_uint2(r20, r21);
            *(uint2*)&KF[fBase + ((3 ^ ktc) << 1)] = make_uint2(r30, r31);
            // V: already bf16 pairs
            const uint32_t* w1 = (const uint32_t*)&vreg[0];
            const uint32_t* w2 = (const uint32_t*)&vreg[1];
            #pragma unroll
            for (int Ti = 0; Ti < 4; Ti++)
                *(uint2*)&VF[fBase + ((Ti ^ ktc) << 1)] = make_uint2(w1[Ti], w2[Ti]);
        }
        __syncthreads();
        if (s0 + 64 < SS) {
            #pragma unroll
            for (int j = 0; j < 4; j++)
                kreg[j] = *(const float4*)(qkv + kS + (size_t)(s0 + 64) * NQKV + j * 4);
            vreg[0] = *(const uint4*)(vrow + s0 + 64);
            vreg[1] = *(const uint4*)(vrow + s0 + 72);
        }

        // S = Q @ K^T (bf16 m16n8k16)
        float sacc[8][4];
        #pragma unroll
        for (int na = 0; na < 8; na++)
            #pragma unroll
            for (int r = 0; r < 4; r++) sacc[na][r] = 0.0f;
        #pragma unroll
        for (int kt = 0; kt < 4; kt++) {
            uint32_t qa[4];
            *(uint4*)qa = *(const uint4*)&QF[((wid * 4 + kt) * 32 + lane) * 4];
            int lx = lane ^ kt;
            #pragma unroll
            for (int na = 0; na < 8; na++) {
                uint32_t kb[2];
                *(uint2*)kb = *(const uint2*)&KF[((na * 4 + kt) * 32 + lx) * 2];
                mma16bf(sacc[na], qa, kb);
            }
        }

        // online softmax (exp2 domain); pack P into bf16 A-fragments
        float rm0 = -1e30f, rm1 = -1e30f;
        #pragma unroll
        for (int na = 0; na < 8; na++) {
            rm0 = fmaxf(rm0, fmaxf(sacc[na][0], sacc[na][1]));
            rm1 = fmaxf(rm1, fmaxf(sacc[na][2], sacc[na][3]));
        }
        rm0 = fmaxf(rm0, __shfl_xor_sync(0xffffffffu, rm0, 1));
        rm0 = fmaxf(rm0, __shfl_xor_sync(0xffffffffu, rm0, 2));
        rm1 = fmaxf(rm1, __shfl_xor_sync(0xffffffffu, rm1, 1));
        rm1 = fmaxf(rm1, __shfl_xor_sync(0xffffffffu, rm1, 2));
        float mn0 = fmaxf(m0, rm0), mn1 = fmaxf(m1, rm1);
        float al0 = exp2f(m0 - mn0), al1 = exp2f(m1 - mn1);
        m0 = mn0; m1 = mn1;
        float rs0 = 0.0f, rs1 = 0.0f;
        uint32_t pregs[4][4];
        #pragma unroll
        for (int na = 0; na < 8; na++) {
            float e0 = exp2f(sacc[na][0] - mn0);
            float e1 = exp2f(sacc[na][1] - mn0);
            float e2 = exp2f(sacc[na][2] - mn1);
            float e3 = exp2f(sacc[na][3] - mn1);
            rs0 += e0 + e1; rs1 += e2 + e3;
            int kt = na >> 1;
            if ((na & 1) == 0) {
                pregs[kt][0] = packbf(e0, e1);
                pregs[kt][1] = packbf(e2, e3);
            } else {
                pregs[kt][2] = packbf(e0, e1);
                pregs[kt][3] = packbf(e2, e3);
            }
        }
        rs0 += __shfl_xor_sync(0xffffffffu, rs0, 1);
        rs0 += __shfl_xor_sync(0xffffffffu, rs0, 2);
        rs1 += __shfl_xor_sync(0xffffffffu, rs1, 1);
        rs1 += __shfl_xor_sync(0xffffffffu, rs1, 2);
        l0 = l0 * al0 + rs0; l1 = l1 * al1 + rs1;
        #pragma unroll
        for (int na = 0; na < 8; na++) {
            oacc[na][0] *= al0; oacc[na][1] *= al0;
            oacc[na][2] *= al1; oacc[na][3] *= al1;
        }

        // O += P @ V (bf16 m16n8k16)
        #pragma unroll
        for (int kt = 0; kt < 4; kt++) {
            int lx = lane ^ kt;
            #pragma unroll
            for (int na = 0; na < 8; na++) {
                uint32_t vb[2];
                *(uint2*)vb = *(const uint2*)&VF[((na * 4 + kt) * 32 + lx) * 2];
                mma16bf(oacc[na], pregs[kt], vb);
            }
        }
    }

    // epilogue (tf32-rounded: feeds O-proj GEMM)
    float inv0 = 1.0f / l0, inv1 = 1.0f / l1;
    int row0 = q0 + wid * 16 + g;
    #pragma unroll
    for (int na = 0; na < 8; na++) {
        int col = h_ * 64 + na * 8 + 2 * T;
        *(float2*)(o + (baseTok + row0)     * DD + col) =
            make_float2(f2tff(oacc[na][0] * inv0), f2tff(oacc[na][1] * inv0));
        *(float2*)(o + (baseTok + row0 + 8) * DD + col) =
            make_float2(f2tff(oacc[na][2] * inv1), f2tff(oacc[na][3] * inv1));
    }
}

// ---------------- launch ---------------------------------------------------
extern "C" void kernel_launch(void* const* d_in, const int* in_sizes, int n_in,
                              void* d_out, int out_size)
{
    (void)in_sizes; (void)n_in; (void)out_size;
    const float* x    = (const float*)d_in[0];
    const float* wq_w = (const float*)d_in[1];
    const float* wq_b = (const float*)d_in[2];
    const float* wk_w = (const float*)d_in[3];
    const float* wk_b = (const float*)d_in[4];
    const float* wv_w = (const float*)d_in[5];
    const float* wv_b = (const float*)d_in[6];
    const float* wo_w = (const float*)d_in[7];
    const float* wo_b = (const float*)d_in[8];
    const float* ln_g = (const float*)d_in[9];
    const float* ln_b = (const float*)d_in[10];
    const float* w1   = (const float*)d_in[11];
    const float* b1   = (const float*)d_in[12];
    const float* w2   = (const float*)d_in[13];
    const float* b2   = (const float*)d_in[14];
    float* out = (float*)d_out;

    float *h, *qkv, *o, *y, *z, *u, *wtq, *btq, *wto, *wt1, *wt2;
    __nv_bfloat16* vt16;
    cudaGetSymbolAddress((void**)&h,    g_h);
    cudaGetSymbolAddress((void**)&qkv,  g_qkv);
    cudaGetSymbolAddress((void**)&vt16, g_vt16);
    cudaGetSymbolAddress((void**)&o,    g_o);
    cudaGetSymbolAddress((void**)&y,    g_y);
    cudaGetSymbolAddress((void**)&z,    g_z);
    cudaGetSymbolAddress((void**)&u,    g_u);
    cudaGetSymbolAddress((void**)&wtq,  g_wtq);
    cudaGetSymbolAddress((void**)&btq,  g_btq);
    cudaGetSymbolAddress((void**)&wto,  g_wto);
    cudaGetSymbolAddress((void**)&wt1,  g_wt1);
    cudaGetSymbolAddress((void**)&wt2,  g_wt2);

    cudaFuncSetAttribute(tc_gemm<false, false, true >, cudaFuncAttributeMaxDynamicSharedMemorySize, GEMM_SMEM);
    cudaFuncSetAttribute(tc_gemm<false, true,  false>, cudaFuncAttributeMaxDynamicSharedMemorySize, GEMM_SMEM);
    cudaFuncSetAttribute(tc_gemm<true,  false, true >, cudaFuncAttributeMaxDynamicSharedMemorySize, GEMM_SMEM);
    cudaFuncSetAttribute(attn_kernel, cudaFuncAttributeMaxDynamicSharedMemorySize, ATTN_SMEM);

    // 0) weight prep
    prep_w_kernel<<<6912, dim3(32, 8)>>>(wq_w, wk_w, wv_w, wo_w, w1, w2,
                                         wtq, wto, wt1, wt2);
    // 1) qkv bias pack
    qkv_bias_kernel<<<3, 256>>>(wq_b, wk_b, wv_b, btq);

    // 2) LN1 (tf32 out)
    ln_kernel<<<MM, 256>>>(x, ln_g, ln_b, h);

    // 3) fused QKV projection (tf32 out)  [capture slot 3 -> ncu]
    tc_gemm<false, false, true><<<dim3(NQKV/128, MM/128), 128, GEMM_SMEM>>>(h, wtq, btq, nullptr, qkv, NQKV, DD);

    // 4) V transpose+bf16 pack
    vtrans_kernel<<<dim3(SS/32, 2, BB*HH), dim3(32, 8)>>>(qkv, vt16);

    // 5) attention (all-bf16 mma)
    attn_kernel<<<dim3(SS/128, BB*HH), 256, ATTN_SMEM>>>(qkv, vt16, o);

    // 6) O-proj + bias + residual(x) -> fp32 y
    tc_gemm<false, true, false><<<dim3(DD/128, MM/128), 128, GEMM_SMEM>>>(o, wto, wo_b, x, y, DD, DD);

    // 7) LN2 (tf32 out)
    ln_kernel<<<MM, 256>>>(y, ln_g, ln_b, z);

    // 8) FFN1 + bias + exact GELU (tf32 out)
    tc_gemm<true, false, true><<<dim3(FF/128, MM/128), 128, GEMM_SMEM>>>(z, wt1, b1, nullptr, u, FF, DD);

    // 9) FFN2 + bias + residual(y) -> out (fp32)
    tc_gemm<false, true, false><<<dim3(DD/128, MM/128), 128, GEMM_SMEM>>>(u, wt2, b2, y, out, DD, FF);
}